// round 8
// baseline (speedup 1.0000x reference)
#include <cuda_runtime.h>
#include <math.h>

#define NN      8192
#define FIN     512
#define HH      8
#define C1      8
#define HC      64      // H*C1
#define NC      16
#define EE      262144
#define CAP     96      // padded adjacency capacity (Poisson(32); P(deg>96) ~ 1e-19)
#define NEG     0.2f

// ---------------- packed f32x2 helpers ----------------
__device__ __forceinline__ float2 ffma2(float2 a, float2 b, float2 c) {
    unsigned long long ra = *reinterpret_cast<unsigned long long*>(&a);
    unsigned long long rb = *reinterpret_cast<unsigned long long*>(&b);
    unsigned long long rc = *reinterpret_cast<unsigned long long*>(&c);
    unsigned long long rd;
    asm("fma.rn.f32x2 %0, %1, %2, %3;" : "=l"(rd) : "l"(ra), "l"(rb), "l"(rc));
    return *reinterpret_cast<float2*>(&rd);
}
__device__ __forceinline__ float2 add2(float2 a, float2 b) {
    unsigned long long ra = *reinterpret_cast<unsigned long long*>(&a);
    unsigned long long rb = *reinterpret_cast<unsigned long long*>(&b);
    unsigned long long rd;
    asm("add.rn.f32x2 %0, %1, %2;" : "=l"(rd) : "l"(ra), "l"(rb));
    return *reinterpret_cast<float2*>(&rd);
}
__device__ __forceinline__ float2 shfl_xor_f2(float2 v, int m) {
    float2 r;
    r.x = __shfl_xor_sync(0xffffffffu, v.x, m);
    r.y = __shfl_xor_sync(0xffffffffu, v.y, m);
    return r;
}

// ---------------- device scratch ----------------
__device__ int   g_cnt [NN];
__device__ int   g_list[NN * CAP];

__device__ float g_h   [NN * HC];
__device__ float g_als1[NN * HH];
__device__ float g_ald1[NN * HH];
__device__ float g_h2  [NN * NC];
__device__ float g_als2[NN];
__device__ float g_ald2[NN];
__device__ float g_z   [NN * NC];

// ---------------- adjacency build (padded, no scan) ----------------
__global__ void k_init() {
    int i = blockIdx.x * blockDim.x + threadIdx.x;
    if (i < NN) {
        g_cnt[i] = 1;            // self-loop pre-appended
        g_list[i * CAP] = i;
    }
}

__global__ void k_scatter(const int* __restrict__ ei) {
    int t = blockIdx.x * blockDim.x + threadIdx.x;
    if (t >= EE / 4) return;
    int e = t * 4;
    int4 s = __ldcs((const int4*)&ei[e]);
    int4 d = __ldcs((const int4*)&ei[EE + e]);
    int p0 = min(atomicAdd(&g_cnt[d.x], 1), CAP - 1);
    g_list[d.x * CAP + p0] = s.x;
    int p1 = min(atomicAdd(&g_cnt[d.y], 1), CAP - 1);
    g_list[d.y * CAP + p1] = s.y;
    int p2 = min(atomicAdd(&g_cnt[d.z], 1), CAP - 1);
    g_list[d.z * CAP + p2] = s.z;
    int p3 = min(atomicAdd(&g_cnt[d.w], 1), CAP - 1);
    g_list[d.w * CAP + p3] = s.w;
}

// ---------------- GEMM1 + fused attention logits ----------------
__global__ void __launch_bounds__(256) k_gemm1(const float* __restrict__ x,
                                               const float* __restrict__ W1,
                                               const float* __restrict__ a_src,
                                               const float* __restrict__ a_dst) {
    __shared__ float xsT[16][68];
    __shared__ float ws[16][64];
    __shared__ float hs[64][68];
    __shared__ float sa[2 * HC];
    int tid = threadIdx.x;
    int row0 = blockIdx.x * 64;
    int tr = tid >> 4;
    int tc = tid & 15;

    if (tid < 2 * HC) sa[tid] = (tid < HC) ? a_src[tid] : a_dst[tid - HC];

    float2 acc[4][2];
#pragma unroll
    for (int i = 0; i < 4; i++)
#pragma unroll
        for (int j = 0; j < 2; j++) acc[i][j] = make_float2(0.f, 0.f);

    int lr = tid >> 2, lc = (tid & 3) * 4;
    int wr = tid >> 4, wc = (tid & 15) * 4;

    for (int k0 = 0; k0 < FIN; k0 += 16) {
        float4 xv = *(const float4*)&x[(size_t)(row0 + lr) * FIN + k0 + lc];
        xsT[lc + 0][lr] = xv.x; xsT[lc + 1][lr] = xv.y;
        xsT[lc + 2][lr] = xv.z; xsT[lc + 3][lr] = xv.w;
        float4 wv = *(const float4*)&W1[(size_t)(k0 + wr) * HC + wc];
        *(float4*)&ws[wr][wc] = wv;
        __syncthreads();
#pragma unroll
        for (int kk = 0; kk < 16; kk++) {
            float4 av = *(const float4*)&xsT[kk][tr * 4];
            float4 bv = *(const float4*)&ws[kk][tc * 4];
            float2 b0 = make_float2(bv.x, bv.y);
            float2 b1 = make_float2(bv.z, bv.w);
            float a[4] = {av.x, av.y, av.z, av.w};
#pragma unroll
            for (int i = 0; i < 4; i++) {
                float2 ad = make_float2(a[i], a[i]);
                acc[i][0] = ffma2(ad, b0, acc[i][0]);
                acc[i][1] = ffma2(ad, b1, acc[i][1]);
            }
        }
        __syncthreads();
    }
#pragma unroll
    for (int i = 0; i < 4; i++) {
        int r = tr * 4 + i;
        float4 v = make_float4(acc[i][0].x, acc[i][0].y, acc[i][1].x, acc[i][1].y);
        *(float4*)&g_h[(size_t)(row0 + r) * HC + tc * 4] = v;
        *(float4*)&hs[r][tc * 4] = v;
    }
    __syncthreads();

    if (tid < 64) {
        const float* hp = hs[tid];
        float als[HH], ald[HH];
#pragma unroll
        for (int h = 0; h < HH; h++) {
            float s = 0.f, d = 0.f;
#pragma unroll
            for (int c = 0; c < C1; c++) {
                float hv = hp[h * C1 + c];
                s = fmaf(hv, sa[h * C1 + c], s);
                d = fmaf(hv, sa[HC + h * C1 + c], d);
            }
            als[h] = s; ald[h] = d;
        }
        size_t b = (size_t)(row0 + tid) * HH;
        *(float4*)&g_als1[b]     = make_float4(als[0], als[1], als[2], als[3]);
        *(float4*)&g_als1[b + 4] = make_float4(als[4], als[5], als[6], als[7]);
        *(float4*)&g_ald1[b]     = make_float4(ald[0], ald[1], ald[2], ald[3]);
        *(float4*)&g_ald1[b + 4] = make_float4(ald[4], ald[5], ald[6], ald[7]);
    }
}

// ---------------- fused agg1 + layer2 transform ----------------
// Block = 256 threads = 2 nodes x 4 warps; warp handles 2 heads (16 channels).
__global__ void __launch_bounds__(256) k_agg1(const float* __restrict__ b1,
                                              const float* __restrict__ W2,
                                              const float* __restrict__ a_src2,
                                              const float* __restrict__ a_dst2) {
    __shared__ float h1s[2][HC];
    __shared__ float w2s[HC * NC];
    int tid = threadIdx.x;
    for (int i = tid; i < HC * NC; i += 256) w2s[i] = W2[i];

    int warp = tid >> 5;
    int lane = tid & 31;
    int nl = warp >> 2;
    int hp = warp & 3;
    int n = blockIdx.x * 2 + nl;
    int o0 = n * CAP;
    int deg = g_cnt[n];

    float2 aldv = *(const float2*)&g_ald1[n * HH + 2 * hp];

    float2 acc[8];
#pragma unroll
    for (int i = 0; i < 8; i++) acc[i] = make_float2(0.f, 0.f);
    float sum0 = 0.f, sum1 = 0.f;

    for (int j = lane; j < deg; j += 32) {
        int s = g_list[o0 + j];
        float2 alsv = *(const float2*)&g_als1[s * HH + 2 * hp];
        float v0 = alsv.x + aldv.x;
        float v1 = alsv.y + aldv.y;
        v0 = fmaxf(v0, NEG * v0);
        v1 = fmaxf(v1, NEG * v1);
        float ex0 = __expf(v0);
        float ex1 = __expf(v1);
        sum0 += ex0; sum1 += ex1;
        const float4* hpnt = (const float4*)&g_h[(size_t)s * HC + hp * 16];
        float4 q0 = hpnt[0], q1 = hpnt[1], q2 = hpnt[2], q3 = hpnt[3];
        float2 e0 = make_float2(ex0, ex0);
        float2 e1 = make_float2(ex1, ex1);
        acc[0] = ffma2(e0, make_float2(q0.x, q0.y), acc[0]);
        acc[1] = ffma2(e0, make_float2(q0.z, q0.w), acc[1]);
        acc[2] = ffma2(e0, make_float2(q1.x, q1.y), acc[2]);
        acc[3] = ffma2(e0, make_float2(q1.z, q1.w), acc[3]);
        acc[4] = ffma2(e1, make_float2(q2.x, q2.y), acc[4]);
        acc[5] = ffma2(e1, make_float2(q2.z, q2.w), acc[5]);
        acc[6] = ffma2(e1, make_float2(q3.x, q3.y), acc[6]);
        acc[7] = ffma2(e1, make_float2(q3.z, q3.w), acc[7]);
    }

    {
#pragma unroll
        for (int i = 0; i < 4; i++) {
            bool hi = (lane & 16) != 0;
            float2 send = hi ? acc[i] : acc[i + 4];
            float2 got = shfl_xor_f2(send, 16);
            float2 keep = hi ? acc[i + 4] : acc[i];
            acc[i] = add2(keep, got);
        }
#pragma unroll
        for (int i = 0; i < 2; i++) {
            bool hi = (lane & 8) != 0;
            float2 send = hi ? acc[i] : acc[i + 2];
            float2 got = shfl_xor_f2(send, 8);
            float2 keep = hi ? acc[i + 2] : acc[i];
            acc[i] = add2(keep, got);
        }
        {
            bool hi = (lane & 4) != 0;
            float2 send = hi ? acc[0] : acc[1];
            float2 got = shfl_xor_f2(send, 4);
            float2 keep = hi ? acc[1] : acc[0];
            acc[0] = add2(keep, got);
        }
    }
    acc[0] = add2(acc[0], shfl_xor_f2(acc[0], 2));
    acc[0] = add2(acc[0], shfl_xor_f2(acc[0], 1));

#pragma unroll
    for (int o = 16; o >= 1; o >>= 1) {
        sum0 += __shfl_xor_sync(0xffffffffu, sum0, o);
        sum1 += __shfl_xor_sync(0xffffffffu, sum1, o);
    }

    int q = lane >> 2;
    float inv = 1.f / ((q < 4) ? sum0 : sum1);
    int ch = hp * 16 + 2 * q;
    float c0 = acc[0].x * inv + b1[ch];
    float c1 = acc[0].y * inv + b1[ch + 1];
    c0 = (c0 > 0.f) ? c0 : (__expf(c0) - 1.f);
    c1 = (c1 > 0.f) ? c1 : (__expf(c1) - 1.f);
    if ((lane & 3) == 0)
        *(float2*)&h1s[nl][ch] = make_float2(c0, c1);
    __syncthreads();

    if (tid < 2 * NC) {
        int tn = tid >> 4;
        int c = tid & 15;
        int gn = blockIdx.x * 2 + tn;
        const float* hp1 = h1s[tn];
        float o = 0.f;
#pragma unroll
        for (int k = 0; k < HC; k++)
            o = fmaf(hp1[k], w2s[k * NC + c], o);
        g_h2[(size_t)gn * NC + c] = o;
        float sv = o * a_src2[c];
        float dv = o * a_dst2[c];
#pragma unroll
        for (int off = 8; off >= 1; off >>= 1) {
            sv += __shfl_xor_sync(0xffffffffu, sv, off);
            dv += __shfl_xor_sync(0xffffffffu, dv, off);
        }
        if (c == 0) {
            g_als2[gn] = sv;
            g_ald2[gn] = dv;
        }
    }
}

// ---------------- layer 2 aggregation + log_softmax fused ----------------
__global__ void k_agg2(const float* __restrict__ b2, float* __restrict__ outls) {
    int warp = threadIdx.x >> 5;
    int lane = threadIdx.x & 31;
    int n = blockIdx.x * 8 + warp;
    int o0 = n * CAP;
    int deg = g_cnt[n];
    float ald = g_ald2[n];

    float2 acc[8];
#pragma unroll
    for (int i = 0; i < 8; i++) acc[i] = make_float2(0.f, 0.f);
    float sumex = 0.f;

    for (int j = lane; j < deg; j += 32) {
        int s = g_list[o0 + j];
        float v = g_als2[s] + ald;
        v = fmaxf(v, NEG * v);
        float ex = __expf(v);
        sumex += ex;
        float2 exd = make_float2(ex, ex);
        const float4* hp = (const float4*)&g_h2[(size_t)s * NC];
#pragma unroll
        for (int qq = 0; qq < 4; qq++) {
            float4 hv = hp[qq];
            acc[qq * 2 + 0] = ffma2(exd, make_float2(hv.x, hv.y), acc[qq * 2 + 0]);
            acc[qq * 2 + 1] = ffma2(exd, make_float2(hv.z, hv.w), acc[qq * 2 + 1]);
        }
    }

    {
#pragma unroll
        for (int i = 0; i < 4; i++) {
            bool hi = (lane & 16) != 0;
            float2 send = hi ? acc[i] : acc[i + 4];
            float2 got = shfl_xor_f2(send, 16);
            float2 keep = hi ? acc[i + 4] : acc[i];
            acc[i] = add2(keep, got);
        }
#pragma unroll
        for (int i = 0; i < 2; i++) {
            bool hi = (lane & 8) != 0;
            float2 send = hi ? acc[i] : acc[i + 2];
            float2 got = shfl_xor_f2(send, 8);
            float2 keep = hi ? acc[i + 2] : acc[i];
            acc[i] = add2(keep, got);
        }
        {
            bool hi = (lane & 4) != 0;
            float2 send = hi ? acc[0] : acc[1];
            float2 got = shfl_xor_f2(send, 4);
            float2 keep = hi ? acc[1] : acc[0];
            acc[0] = add2(keep, got);
        }
    }
    acc[0] = add2(acc[0], shfl_xor_f2(acc[0], 2));
    acc[0] = add2(acc[0], shfl_xor_f2(acc[0], 1));

#pragma unroll
    for (int o = 16; o >= 1; o >>= 1) sumex += __shfl_xor_sync(0xffffffffu, sumex, o);

    int p = lane >> 2;
    float inv = 1.f / sumex;
    float z0 = acc[0].x * inv + b2[2 * p];
    float z1 = acc[0].y * inv + b2[2 * p + 1];

    float m = fmaxf(z0, z1);
#pragma unroll
    for (int o = 16; o >= 1; o >>= 1) m = fmaxf(m, __shfl_xor_sync(0xffffffffu, m, o));
    float se2 = __expf(z0 - m) + __expf(z1 - m);
#pragma unroll
    for (int o = 16; o >= 1; o >>= 1) se2 += __shfl_xor_sync(0xffffffffu, se2, o);
    se2 *= 0.25f;
    float lse = m + __logf(se2);

    if ((lane & 3) == 0) {
        *(float2*)&g_z[(size_t)n * NC + 2 * p] = make_float2(z0, z1);
        *(float2*)&outls[(size_t)n * NC + 2 * p] = make_float2(z0 - lse, z1 - lse);
    }
}

// ---------------- Gram: G = z @ z.T, FFMA2, streaming stores ----------------
__global__ void __launch_bounds__(256) k_gram(float* __restrict__ out) {
    __shared__ float zrT[NC][128];
    __shared__ float zcT[NC][128];
    int tid = threadIdx.x;
    int row0 = blockIdx.y * 128;
    int col0 = blockIdx.x * 128;

    {
        int r = tid >> 1;
        int kg = (tid & 1) * 8;
        float4 v0 = *(const float4*)&g_z[(size_t)(row0 + r) * NC + kg];
        float4 v1 = *(const float4*)&g_z[(size_t)(row0 + r) * NC + kg + 4];
        zrT[kg + 0][r] = v0.x; zrT[kg + 1][r] = v0.y; zrT[kg + 2][r] = v0.z; zrT[kg + 3][r] = v0.w;
        zrT[kg + 4][r] = v1.x; zrT[kg + 5][r] = v1.y; zrT[kg + 6][r] = v1.z; zrT[kg + 7][r] = v1.w;
        float4 u0 = *(const float4*)&g_z[(size_t)(col0 + r) * NC + kg];
        float4 u1 = *(const float4*)&g_z[(size_t)(col0 + r) * NC + kg + 4];
        zcT[kg + 0][r] = u0.x; zcT[kg + 1][r] = u0.y; zcT[kg + 2][r] = u0.z; zcT[kg + 3][r] = u0.w;
        zcT[kg + 4][r] = u1.x; zcT[kg + 5][r] = u1.y; zcT[kg + 6][r] = u1.z; zcT[kg + 7][r] = u1.w;
    }
    __syncthreads();

    int ty = tid >> 4, tx = tid & 15;
    int rr = ty * 8, cc = tx * 8;
    float2 acc[8][4];
#pragma unroll
    for (int i = 0; i < 8; i++)
#pragma unroll
        for (int j = 0; j < 4; j++) acc[i][j] = make_float2(0.f, 0.f);

#pragma unroll
    for (int k = 0; k < NC; k++) {
        float4 a04 = *(const float4*)&zrT[k][rr];
        float4 a48 = *(const float4*)&zrT[k][rr + 4];
        float a[8] = {a04.x, a04.y, a04.z, a04.w, a48.x, a48.y, a48.z, a48.w};
        float4 b04 = *(const float4*)&zcT[k][cc];
        float4 b48 = *(const float4*)&zcT[k][cc + 4];
        float2 b[4] = {make_float2(b04.x, b04.y), make_float2(b04.z, b04.w),
                       make_float2(b48.x, b48.y), make_float2(b48.z, b48.w)};
#pragma unroll
        for (int i = 0; i < 8; i++) {
            float2 adup = make_float2(a[i], a[i]);
#pragma unroll
            for (int j = 0; j < 4; j++)
                acc[i][j] = ffma2(adup, b[j], acc[i][j]);
        }
    }

#pragma unroll
    for (int i = 0; i < 8; i++) {
        size_t base = (size_t)(row0 + rr + i) * NN + col0 + cc;
        float4 v0 = make_float4(acc[i][0].x, acc[i][0].y, acc[i][1].x, acc[i][1].y);
        float4 v1 = make_float4(acc[i][2].x, acc[i][2].y, acc[i][3].x, acc[i][3].y);
        __stcs((float4*)&out[base], v0);
        __stcs((float4*)&out[base + 4], v1);
    }
}

// ---------------- launch ----------------
extern "C" void kernel_launch(void* const* d_in, const int* in_sizes, int n_in,
                              void* d_out, int out_size) {
    const float* x      = (const float*)d_in[0];
    const int*   ei     = (const int*)  d_in[1];
    const float* W1     = (const float*)d_in[2];
    const float* a_src1 = (const float*)d_in[3];
    const float* a_dst1 = (const float*)d_in[4];
    const float* b1     = (const float*)d_in[5];
    const float* W2     = (const float*)d_in[6];
    const float* a_src2 = (const float*)d_in[7];
    const float* a_dst2 = (const float*)d_in[8];
    const float* b2     = (const float*)d_in[9];
    float* out = (float*)d_out;

    static cudaStream_t sA = nullptr;
    static cudaEvent_t evFork = nullptr, evA = nullptr;
    if (sA == nullptr) {
        cudaStreamCreateWithFlags(&sA, cudaStreamNonBlocking);
        cudaEventCreateWithFlags(&evFork, cudaEventDisableTiming);
        cudaEventCreateWithFlags(&evA, cudaEventDisableTiming);
    }

    // fork: adjacency build on sA overlapped with GEMM1 on main
    cudaEventRecord(evFork, 0);
    cudaStreamWaitEvent(sA, evFork, 0);

    k_init<<<NN / 256, 256, 0, sA>>>();                 // launch 1
    k_gemm1<<<NN / 64, 256>>>(x, W1, a_src1, a_dst1);   // launch 2 (main)
    k_scatter<<<EE / 4 / 256, 256, 0, sA>>>(ei);        // launch 3
    cudaEventRecord(evA, sA);
    cudaStreamWaitEvent(0, evA, 0);

    k_agg1<<<NN / 2, 256>>>(b1, W2, a_src2, a_dst2);    // launch 4  <- profiled slot
    k_agg2<<<NN / 8, 256>>>(b2, out);                   // launch 5
    k_gram<<<dim3(NN / 128, NN / 128), 256>>>(out + (size_t)NN * NC);  // launch 6
}

// round 9
// speedup vs baseline: 1.0290x; 1.0290x over previous
#include <cuda_runtime.h>
#include <math.h>

#define NN      8192
#define FIN     512
#define HH      8
#define C1      8
#define HC      64      // H*C1
#define NC      16
#define EE      262144
#define CAP     128     // padded adjacency capacity, 512B-aligned rows
#define NEG     0.2f

// ---------------- packed f32x2 helpers ----------------
__device__ __forceinline__ float2 ffma2(float2 a, float2 b, float2 c) {
    unsigned long long ra = *reinterpret_cast<unsigned long long*>(&a);
    unsigned long long rb = *reinterpret_cast<unsigned long long*>(&b);
    unsigned long long rc = *reinterpret_cast<unsigned long long*>(&c);
    unsigned long long rd;
    asm("fma.rn.f32x2 %0, %1, %2, %3;" : "=l"(rd) : "l"(ra), "l"(rb), "l"(rc));
    return *reinterpret_cast<float2*>(&rd);
}
__device__ __forceinline__ float2 add2(float2 a, float2 b) {
    unsigned long long ra = *reinterpret_cast<unsigned long long*>(&a);
    unsigned long long rb = *reinterpret_cast<unsigned long long*>(&b);
    unsigned long long rd;
    asm("add.rn.f32x2 %0, %1, %2;" : "=l"(rd) : "l"(ra), "l"(rb));
    return *reinterpret_cast<float2*>(&rd);
}
__device__ __forceinline__ float2 shfl_xor_f2(float2 v, int m) {
    float2 r;
    r.x = __shfl_xor_sync(0xffffffffu, v.x, m);
    r.y = __shfl_xor_sync(0xffffffffu, v.y, m);
    return r;
}

// ---------------- device scratch ----------------
__device__ int   g_cnt [NN];
__device__ int   g_list[NN * CAP];

__device__ float g_h   [NN * HC];
__device__ float g_als1[NN * HH];
__device__ float g_ald1[NN * HH];
__device__ float g_h2  [NN * NC];
__device__ float g_als2[NN];
__device__ float g_ald2[NN];
__device__ float g_z   [NN * NC];

// ---------------- adjacency build (padded, no scan) ----------------
__global__ void k_init() {
    int i = blockIdx.x * blockDim.x + threadIdx.x;
    if (i < NN) {
        g_cnt[i] = 1;            // self-loop pre-appended
        g_list[i * CAP] = i;
    }
}

__global__ void k_scatter(const int* __restrict__ ei) {
    int t = blockIdx.x * blockDim.x + threadIdx.x;
    if (t >= EE / 4) return;
    int e = t * 4;
    int4 s = __ldcs((const int4*)&ei[e]);
    int4 d = __ldcs((const int4*)&ei[EE + e]);
    int p0 = min(atomicAdd(&g_cnt[d.x], 1), CAP - 1);
    g_list[d.x * CAP + p0] = s.x;
    int p1 = min(atomicAdd(&g_cnt[d.y], 1), CAP - 1);
    g_list[d.y * CAP + p1] = s.y;
    int p2 = min(atomicAdd(&g_cnt[d.z], 1), CAP - 1);
    g_list[d.z * CAP + p2] = s.z;
    int p3 = min(atomicAdd(&g_cnt[d.w], 1), CAP - 1);
    g_list[d.w * CAP + p3] = s.w;
}

// ---------------- GEMM1 + fused attention logits ----------------
__global__ void __launch_bounds__(256) k_gemm1(const float* __restrict__ x,
                                               const float* __restrict__ W1,
                                               const float* __restrict__ a_src,
                                               const float* __restrict__ a_dst) {
    __shared__ float xsT[16][68];
    __shared__ float ws[16][64];
    __shared__ float hs[64][68];
    __shared__ float sa[2 * HC];
    int tid = threadIdx.x;
    int row0 = blockIdx.x * 64;
    int tr = tid >> 4;
    int tc = tid & 15;

    if (tid < 2 * HC) sa[tid] = (tid < HC) ? a_src[tid] : a_dst[tid - HC];

    float2 acc[4][2];
#pragma unroll
    for (int i = 0; i < 4; i++)
#pragma unroll
        for (int j = 0; j < 2; j++) acc[i][j] = make_float2(0.f, 0.f);

    int lr = tid >> 2, lc = (tid & 3) * 4;
    int wr = tid >> 4, wc = (tid & 15) * 4;

    for (int k0 = 0; k0 < FIN; k0 += 16) {
        float4 xv = *(const float4*)&x[(size_t)(row0 + lr) * FIN + k0 + lc];
        xsT[lc + 0][lr] = xv.x; xsT[lc + 1][lr] = xv.y;
        xsT[lc + 2][lr] = xv.z; xsT[lc + 3][lr] = xv.w;
        float4 wv = *(const float4*)&W1[(size_t)(k0 + wr) * HC + wc];
        *(float4*)&ws[wr][wc] = wv;
        __syncthreads();
#pragma unroll
        for (int kk = 0; kk < 16; kk++) {
            float4 av = *(const float4*)&xsT[kk][tr * 4];
            float4 bv = *(const float4*)&ws[kk][tc * 4];
            float2 b0 = make_float2(bv.x, bv.y);
            float2 b1 = make_float2(bv.z, bv.w);
            float a[4] = {av.x, av.y, av.z, av.w};
#pragma unroll
            for (int i = 0; i < 4; i++) {
                float2 ad = make_float2(a[i], a[i]);
                acc[i][0] = ffma2(ad, b0, acc[i][0]);
                acc[i][1] = ffma2(ad, b1, acc[i][1]);
            }
        }
        __syncthreads();
    }
#pragma unroll
    for (int i = 0; i < 4; i++) {
        int r = tr * 4 + i;
        float4 v = make_float4(acc[i][0].x, acc[i][0].y, acc[i][1].x, acc[i][1].y);
        *(float4*)&g_h[(size_t)(row0 + r) * HC + tc * 4] = v;
        *(float4*)&hs[r][tc * 4] = v;
    }
    __syncthreads();

    if (tid < 64) {
        const float* hp = hs[tid];
        float als[HH], ald[HH];
#pragma unroll
        for (int h = 0; h < HH; h++) {
            float s = 0.f, d = 0.f;
#pragma unroll
            for (int c = 0; c < C1; c++) {
                float hv = hp[h * C1 + c];
                s = fmaf(hv, sa[h * C1 + c], s);
                d = fmaf(hv, sa[HC + h * C1 + c], d);
            }
            als[h] = s; ald[h] = d;
        }
        size_t b = (size_t)(row0 + tid) * HH;
        *(float4*)&g_als1[b]     = make_float4(als[0], als[1], als[2], als[3]);
        *(float4*)&g_als1[b + 4] = make_float4(als[4], als[5], als[6], als[7]);
        *(float4*)&g_ald1[b]     = make_float4(ald[0], ald[1], ald[2], ald[3]);
        *(float4*)&g_ald1[b + 4] = make_float4(ald[4], ald[5], ald[6], ald[7]);
    }
}

// ---------------- fused agg1 + layer2 transform (quad-cooperative gather) ----------------
// Block = 256 threads = 2 nodes x 4 warps; warp handles 2 heads (16 channels).
// Within a warp: 8 neighbor-groups of 4 lanes; each quad loads ONE neighbor's
// 64B feature chunk coalesced (16B/lane) -> 1 L1 wavefront per neighbor.
__global__ void __launch_bounds__(256) k_agg1(const float* __restrict__ b1,
                                              const float* __restrict__ W2,
                                              const float* __restrict__ a_src2,
                                              const float* __restrict__ a_dst2) {
    __shared__ float h1s[2][HC];
    __shared__ float w2s[HC * NC];
    int tid = threadIdx.x;
    for (int i = tid; i < HC * NC; i += 256) w2s[i] = W2[i];

    int warp = tid >> 5;
    int lane = tid & 31;
    int nl = warp >> 2;
    int hp = warp & 3;
    int n = blockIdx.x * 2 + nl;
    int o0 = n * CAP;
    int deg = min(g_cnt[n], CAP);
    int g = lane >> 2;          // neighbor group 0..7
    int sub = lane & 3;         // float4 slice within 64B chunk

    float2 aldv = *(const float2*)&g_ald1[n * HH + 2 * hp];

    float2 acc0 = make_float2(0.f, 0.f), acc1 = make_float2(0.f, 0.f);
    float sum0 = 0.f, sum1 = 0.f;

    for (int base = 0; base < deg; base += 8) {
        int j = base + g;
        if (j < deg) {
            int s = g_list[o0 + j];
            float2 alsv = *(const float2*)&g_als1[s * HH + 2 * hp];
            float v0 = alsv.x + aldv.x;
            float v1 = alsv.y + aldv.y;
            v0 = fmaxf(v0, NEG * v0);
            v1 = fmaxf(v1, NEG * v1);
            float ex0 = __expf(v0);
            float ex1 = __expf(v1);
            sum0 += ex0; sum1 += ex1;
            float4 q = *(const float4*)&g_h[(size_t)s * HC + hp * 16 + sub * 4];
            float exs = (sub < 2) ? ex0 : ex1;   // slices 0,1 -> head 2hp; 2,3 -> head 2hp+1
            float2 e = make_float2(exs, exs);
            acc0 = ffma2(e, make_float2(q.x, q.y), acc0);
            acc1 = ffma2(e, make_float2(q.z, q.w), acc1);
        }
    }

    // reduce across the 8 neighbor groups (lane bits 2,3,4)
    acc0 = add2(acc0, shfl_xor_f2(acc0, 4));
    acc0 = add2(acc0, shfl_xor_f2(acc0, 8));
    acc0 = add2(acc0, shfl_xor_f2(acc0, 16));
    acc1 = add2(acc1, shfl_xor_f2(acc1, 4));
    acc1 = add2(acc1, shfl_xor_f2(acc1, 8));
    acc1 = add2(acc1, shfl_xor_f2(acc1, 16));
    sum0 += __shfl_xor_sync(0xffffffffu, sum0, 4);
    sum0 += __shfl_xor_sync(0xffffffffu, sum0, 8);
    sum0 += __shfl_xor_sync(0xffffffffu, sum0, 16);
    sum1 += __shfl_xor_sync(0xffffffffu, sum1, 4);
    sum1 += __shfl_xor_sync(0xffffffffu, sum1, 8);
    sum1 += __shfl_xor_sync(0xffffffffu, sum1, 16);

    float inv = 1.f / ((sub < 2) ? sum0 : sum1);
    int ch = hp * 16 + sub * 4;
    float c0 = acc0.x * inv + b1[ch + 0];
    float c1 = acc0.y * inv + b1[ch + 1];
    float c2 = acc1.x * inv + b1[ch + 2];
    float c3 = acc1.y * inv + b1[ch + 3];
    c0 = (c0 > 0.f) ? c0 : (__expf(c0) - 1.f);
    c1 = (c1 > 0.f) ? c1 : (__expf(c1) - 1.f);
    c2 = (c2 > 0.f) ? c2 : (__expf(c2) - 1.f);
    c3 = (c3 > 0.f) ? c3 : (__expf(c3) - 1.f);
    if (lane < 4)
        *(float4*)&h1s[nl][ch] = make_float4(c0, c1, c2, c3);
    __syncthreads();

    // layer-2 transform: 32 threads (2 nodes x 16 classes)
    if (tid < 2 * NC) {
        int tn = tid >> 4;
        int c = tid & 15;
        int gn = blockIdx.x * 2 + tn;
        const float* hp1 = h1s[tn];
        float o = 0.f;
#pragma unroll
        for (int k = 0; k < HC; k++)
            o = fmaf(hp1[k], w2s[k * NC + c], o);
        g_h2[(size_t)gn * NC + c] = o;
        float sv = o * a_src2[c];
        float dv = o * a_dst2[c];
#pragma unroll
        for (int off = 8; off >= 1; off >>= 1) {
            sv += __shfl_xor_sync(0xffffffffu, sv, off);
            dv += __shfl_xor_sync(0xffffffffu, dv, off);
        }
        if (c == 0) {
            g_als2[gn] = sv;
            g_ald2[gn] = dv;
        }
    }
}

// ---------------- layer 2 aggregation + log_softmax (quad-cooperative) ----------------
__global__ void k_agg2(const float* __restrict__ b2, float* __restrict__ outls) {
    int warp = threadIdx.x >> 5;
    int lane = threadIdx.x & 31;
    int n = blockIdx.x * 8 + warp;
    int o0 = n * CAP;
    int deg = min(g_cnt[n], CAP);
    float ald = g_ald2[n];
    int g = lane >> 2;
    int sub = lane & 3;

    float2 acc0 = make_float2(0.f, 0.f), acc1 = make_float2(0.f, 0.f);
    float sumex = 0.f;

    for (int base = 0; base < deg; base += 8) {
        int j = base + g;
        if (j < deg) {
            int s = g_list[o0 + j];
            float v = g_als2[s] + ald;
            v = fmaxf(v, NEG * v);
            float ex = __expf(v);
            sumex += ex;
            float4 q = *(const float4*)&g_h2[(size_t)s * NC + sub * 4];
            float2 e = make_float2(ex, ex);
            acc0 = ffma2(e, make_float2(q.x, q.y), acc0);
            acc1 = ffma2(e, make_float2(q.z, q.w), acc1);
        }
    }

    acc0 = add2(acc0, shfl_xor_f2(acc0, 4));
    acc0 = add2(acc0, shfl_xor_f2(acc0, 8));
    acc0 = add2(acc0, shfl_xor_f2(acc0, 16));
    acc1 = add2(acc1, shfl_xor_f2(acc1, 4));
    acc1 = add2(acc1, shfl_xor_f2(acc1, 8));
    acc1 = add2(acc1, shfl_xor_f2(acc1, 16));
    sumex += __shfl_xor_sync(0xffffffffu, sumex, 4);
    sumex += __shfl_xor_sync(0xffffffffu, sumex, 8);
    sumex += __shfl_xor_sync(0xffffffffu, sumex, 16);

    float inv = 1.f / sumex;
    float z0 = acc0.x * inv + b2[sub * 4 + 0];
    float z1 = acc0.y * inv + b2[sub * 4 + 1];
    float z2 = acc1.x * inv + b2[sub * 4 + 2];
    float z3 = acc1.y * inv + b2[sub * 4 + 3];

    // log_softmax over 16 channels: each quad's 4 lanes hold 4 distinct channels
    float m = fmaxf(fmaxf(z0, z1), fmaxf(z2, z3));
    m = fmaxf(m, __shfl_xor_sync(0xffffffffu, m, 1));
    m = fmaxf(m, __shfl_xor_sync(0xffffffffu, m, 2));
    float se = __expf(z0 - m) + __expf(z1 - m) + __expf(z2 - m) + __expf(z3 - m);
    se += __shfl_xor_sync(0xffffffffu, se, 1);
    se += __shfl_xor_sync(0xffffffffu, se, 2);
    float lse = m + __logf(se);

    if (lane < 4) {
        *(float4*)&g_z[(size_t)n * NC + sub * 4] = make_float4(z0, z1, z2, z3);
        *(float4*)&outls[(size_t)n * NC + sub * 4] =
            make_float4(z0 - lse, z1 - lse, z2 - lse, z3 - lse);
    }
}

// ---------------- Gram: G = z @ z.T, FFMA2, streaming stores ----------------
__global__ void __launch_bounds__(256) k_gram(float* __restrict__ out) {
    __shared__ float zrT[NC][128];
    __shared__ float zcT[NC][128];
    int tid = threadIdx.x;
    int row0 = blockIdx.y * 128;
    int col0 = blockIdx.x * 128;

    {
        int r = tid >> 1;
        int kg = (tid & 1) * 8;
        float4 v0 = *(const float4*)&g_z[(size_t)(row0 + r) * NC + kg];
        float4 v1 = *(const float4*)&g_z[(size_t)(row0 + r) * NC + kg + 4];
        zrT[kg + 0][r] = v0.x; zrT[kg + 1][r] = v0.y; zrT[kg + 2][r] = v0.z; zrT[kg + 3][r] = v0.w;
        zrT[kg + 4][r] = v1.x; zrT[kg + 5][r] = v1.y; zrT[kg + 6][r] = v1.z; zrT[kg + 7][r] = v1.w;
        float4 u0 = *(const float4*)&g_z[(size_t)(col0 + r) * NC + kg];
        float4 u1 = *(const float4*)&g_z[(size_t)(col0 + r) * NC + kg + 4];
        zcT[kg + 0][r] = u0.x; zcT[kg + 1][r] = u0.y; zcT[kg + 2][r] = u0.z; zcT[kg + 3][r] = u0.w;
        zcT[kg + 4][r] = u1.x; zcT[kg + 5][r] = u1.y; zcT[kg + 6][r] = u1.z; zcT[kg + 7][r] = u1.w;
    }
    __syncthreads();

    int ty = tid >> 4, tx = tid & 15;
    int rr = ty * 8, cc = tx * 8;
    float2 acc[8][4];
#pragma unroll
    for (int i = 0; i < 8; i++)
#pragma unroll
        for (int j = 0; j < 4; j++) acc[i][j] = make_float2(0.f, 0.f);

#pragma unroll
    for (int k = 0; k < NC; k++) {
        float4 a04 = *(const float4*)&zrT[k][rr];
        float4 a48 = *(const float4*)&zrT[k][rr + 4];
        float a[8] = {a04.x, a04.y, a04.z, a04.w, a48.x, a48.y, a48.z, a48.w};
        float4 b04 = *(const float4*)&zcT[k][cc];
        float4 b48 = *(const float4*)&zcT[k][cc + 4];
        float2 b[4] = {make_float2(b04.x, b04.y), make_float2(b04.z, b04.w),
                       make_float2(b48.x, b48.y), make_float2(b48.z, b48.w)};
#pragma unroll
        for (int i = 0; i < 8; i++) {
            float2 adup = make_float2(a[i], a[i]);
#pragma unroll
            for (int j = 0; j < 4; j++)
                acc[i][j] = ffma2(adup, b[j], acc[i][j]);
        }
    }

#pragma unroll
    for (int i = 0; i < 8; i++) {
        size_t base = (size_t)(row0 + rr + i) * NN + col0 + cc;
        float4 v0 = make_float4(acc[i][0].x, acc[i][0].y, acc[i][1].x, acc[i][1].y);
        float4 v1 = make_float4(acc[i][2].x, acc[i][2].y, acc[i][3].x, acc[i][3].y);
        __stcs((float4*)&out[base], v0);
        __stcs((float4*)&out[base + 4], v1);
    }
}

// ---------------- launch ----------------
extern "C" void kernel_launch(void* const* d_in, const int* in_sizes, int n_in,
                              void* d_out, int out_size) {
    const float* x      = (const float*)d_in[0];
    const int*   ei     = (const int*)  d_in[1];
    const float* W1     = (const float*)d_in[2];
    const float* a_src1 = (const float*)d_in[3];
    const float* a_dst1 = (const float*)d_in[4];
    const float* b1     = (const float*)d_in[5];
    const float* W2     = (const float*)d_in[6];
    const float* a_src2 = (const float*)d_in[7];
    const float* a_dst2 = (const float*)d_in[8];
    const float* b2     = (const float*)d_in[9];
    float* out = (float*)d_out;

    static cudaStream_t sA = nullptr;
    static cudaEvent_t evFork = nullptr, evA = nullptr;
    if (sA == nullptr) {
        cudaStreamCreateWithFlags(&sA, cudaStreamNonBlocking);
        cudaEventCreateWithFlags(&evFork, cudaEventDisableTiming);
        cudaEventCreateWithFlags(&evA, cudaEventDisableTiming);
    }

    // fork: adjacency build on sA overlapped with GEMM1 on main
    cudaEventRecord(evFork, 0);
    cudaStreamWaitEvent(sA, evFork, 0);

    k_init<<<NN / 256, 256, 0, sA>>>();                 // launch 1
    k_gemm1<<<NN / 64, 256>>>(x, W1, a_src1, a_dst1);   // launch 2 (main)
    k_scatter<<<EE / 4 / 256, 256, 0, sA>>>(ei);        // launch 3
    cudaEventRecord(evA, sA);
    cudaStreamWaitEvent(0, evA, 0);

    k_agg1<<<NN / 2, 256>>>(b1, W2, a_src2, a_dst2);    // launch 4  <- profiled slot
    k_agg2<<<NN / 8, 256>>>(b2, out);                   // launch 5
    k_gram<<<dim3(NN / 128, NN / 128), 256>>>(out + (size_t)NN * NC);  // launch 6
}

// round 10
// speedup vs baseline: 1.1392x; 1.1070x over previous
#include <cuda_runtime.h>
#include <math.h>

#define NN      8192
#define FIN     512
#define HH      8
#define C1      8
#define HC      64      // H*C1
#define NC      16
#define EE      262144
#define CAP     128     // padded adjacency capacity, 512B-aligned rows
#define NEG     0.2f

// ---------------- packed f32x2 helpers ----------------
__device__ __forceinline__ float2 ffma2(float2 a, float2 b, float2 c) {
    unsigned long long ra = *reinterpret_cast<unsigned long long*>(&a);
    unsigned long long rb = *reinterpret_cast<unsigned long long*>(&b);
    unsigned long long rc = *reinterpret_cast<unsigned long long*>(&c);
    unsigned long long rd;
    asm("fma.rn.f32x2 %0, %1, %2, %3;" : "=l"(rd) : "l"(ra), "l"(rb), "l"(rc));
    return *reinterpret_cast<float2*>(&rd);
}
__device__ __forceinline__ float2 add2(float2 a, float2 b) {
    unsigned long long ra = *reinterpret_cast<unsigned long long*>(&a);
    unsigned long long rb = *reinterpret_cast<unsigned long long*>(&b);
    unsigned long long rd;
    asm("add.rn.f32x2 %0, %1, %2;" : "=l"(rd) : "l"(ra), "l"(rb));
    return *reinterpret_cast<float2*>(&rd);
}
__device__ __forceinline__ float2 shfl_xor_f2(float2 v, int m) {
    float2 r;
    r.x = __shfl_xor_sync(0xffffffffu, v.x, m);
    r.y = __shfl_xor_sync(0xffffffffu, v.y, m);
    return r;
}

// ---------------- device scratch ----------------
__device__ int   g_cnt [NN];
__device__ int   g_list[NN * CAP];

__device__ float g_h   [NN * HC];
__device__ float g_als1[NN * HH];
__device__ float g_ald1[NN * HH];
__device__ float g_h2  [NN * NC];
__device__ float g_als2[NN];
__device__ float g_ald2[NN];
__device__ float g_z   [NN * NC];

// ---------------- adjacency build (padded, no scan) ----------------
__global__ void k_init() {
    int i = blockIdx.x * blockDim.x + threadIdx.x;
    if (i < NN) {
        g_cnt[i] = 1;            // self-loop pre-appended
        g_list[i * CAP] = i;
    }
}

__global__ void k_scatter(const int* __restrict__ ei) {
    int t = blockIdx.x * blockDim.x + threadIdx.x;
    if (t >= EE / 4) return;
    int e = t * 4;
    int4 s = __ldcs((const int4*)&ei[e]);
    int4 d = __ldcs((const int4*)&ei[EE + e]);
    int p0 = min(atomicAdd(&g_cnt[d.x], 1), CAP - 1);
    g_list[d.x * CAP + p0] = s.x;
    int p1 = min(atomicAdd(&g_cnt[d.y], 1), CAP - 1);
    g_list[d.y * CAP + p1] = s.y;
    int p2 = min(atomicAdd(&g_cnt[d.z], 1), CAP - 1);
    g_list[d.z * CAP + p2] = s.z;
    int p3 = min(atomicAdd(&g_cnt[d.w], 1), CAP - 1);
    g_list[d.w * CAP + p3] = s.w;
}

// ---------------- GEMM1 + fused attention logits (double-buffered loads) ----------------
__global__ void __launch_bounds__(256) k_gemm1(const float* __restrict__ x,
                                               const float* __restrict__ W1,
                                               const float* __restrict__ a_src,
                                               const float* __restrict__ a_dst) {
    __shared__ float xsT[16][68];
    __shared__ float ws[16][64];
    __shared__ float hs[64][68];
    __shared__ float sa[2 * HC];
    int tid = threadIdx.x;
    int row0 = blockIdx.x * 64;
    int tr = tid >> 4;
    int tc = tid & 15;

    if (tid < 2 * HC) sa[tid] = (tid < HC) ? a_src[tid] : a_dst[tid - HC];

    float2 acc[4][2];
#pragma unroll
    for (int i = 0; i < 4; i++)
#pragma unroll
        for (int j = 0; j < 2; j++) acc[i][j] = make_float2(0.f, 0.f);

    int lr = tid >> 2, lc = (tid & 3) * 4;
    int wr = tid >> 4, wc = (tid & 15) * 4;

    // prefetch stage 0
    float4 xv = *(const float4*)&x[(size_t)(row0 + lr) * FIN + lc];
    float4 wv = *(const float4*)&W1[(size_t)wr * HC + wc];

    for (int k0 = 0; k0 < FIN; k0 += 16) {
        xsT[lc + 0][lr] = xv.x; xsT[lc + 1][lr] = xv.y;
        xsT[lc + 2][lr] = xv.z; xsT[lc + 3][lr] = xv.w;
        *(float4*)&ws[wr][wc] = wv;
        __syncthreads();
        if (k0 + 16 < FIN) {   // prefetch next stage while computing
            xv = *(const float4*)&x[(size_t)(row0 + lr) * FIN + k0 + 16 + lc];
            wv = *(const float4*)&W1[(size_t)(k0 + 16 + wr) * HC + wc];
        }
#pragma unroll
        for (int kk = 0; kk < 16; kk++) {
            float4 av = *(const float4*)&xsT[kk][tr * 4];
            float4 bv = *(const float4*)&ws[kk][tc * 4];
            float2 b0 = make_float2(bv.x, bv.y);
            float2 b1 = make_float2(bv.z, bv.w);
            float a[4] = {av.x, av.y, av.z, av.w};
#pragma unroll
            for (int i = 0; i < 4; i++) {
                float2 ad = make_float2(a[i], a[i]);
                acc[i][0] = ffma2(ad, b0, acc[i][0]);
                acc[i][1] = ffma2(ad, b1, acc[i][1]);
            }
        }
        __syncthreads();
    }
#pragma unroll
    for (int i = 0; i < 4; i++) {
        int r = tr * 4 + i;
        float4 v = make_float4(acc[i][0].x, acc[i][0].y, acc[i][1].x, acc[i][1].y);
        *(float4*)&g_h[(size_t)(row0 + r) * HC + tc * 4] = v;
        *(float4*)&hs[r][tc * 4] = v;
    }
    __syncthreads();

    if (tid < 64) {
        const float* hp = hs[tid];
        float als[HH], ald[HH];
#pragma unroll
        for (int h = 0; h < HH; h++) {
            float s = 0.f, d = 0.f;
#pragma unroll
            for (int c = 0; c < C1; c++) {
                float hv = hp[h * C1 + c];
                s = fmaf(hv, sa[h * C1 + c], s);
                d = fmaf(hv, sa[HC + h * C1 + c], d);
            }
            als[h] = s; ald[h] = d;
        }
        size_t b = (size_t)(row0 + tid) * HH;
        *(float4*)&g_als1[b]     = make_float4(als[0], als[1], als[2], als[3]);
        *(float4*)&g_als1[b + 4] = make_float4(als[4], als[5], als[6], als[7]);
        *(float4*)&g_ald1[b]     = make_float4(ald[0], ald[1], ald[2], ald[3]);
        *(float4*)&g_ald1[b + 4] = make_float4(ald[4], ald[5], ald[6], ald[7]);
    }
}

// ---------------- fused agg1 + layer2 transform (quad-cooperative gather) ----------------
// Block = 256 threads = 2 nodes x 4 warps; warp handles 2 heads (16 channels).
__global__ void __launch_bounds__(256) k_agg1(const float* __restrict__ b1,
                                              const float* __restrict__ W2,
                                              const float* __restrict__ a_src2,
                                              const float* __restrict__ a_dst2) {
    __shared__ float h1s[2][HC];
    int tid = threadIdx.x;
    int warp = tid >> 5;
    int lane = tid & 31;
    int nl = warp >> 2;
    int hp = warp & 3;
    int n = blockIdx.x * 2 + nl;
    int o0 = n * CAP;
    int deg = min(g_cnt[n], CAP);
    int g = lane >> 2;          // neighbor group 0..7
    int sub = lane & 3;         // float4 slice within 64B chunk

    float2 aldv = *(const float2*)&g_ald1[n * HH + 2 * hp];

    float2 acc0 = make_float2(0.f, 0.f), acc1 = make_float2(0.f, 0.f);
    float sum0 = 0.f, sum1 = 0.f;

    for (int base = 0; base < deg; base += 8) {
        int j = base + g;
        if (j < deg) {
            int s = g_list[o0 + j];
            float2 alsv = *(const float2*)&g_als1[s * HH + 2 * hp];
            float v0 = alsv.x + aldv.x;
            float v1 = alsv.y + aldv.y;
            v0 = fmaxf(v0, NEG * v0);
            v1 = fmaxf(v1, NEG * v1);
            float ex0 = __expf(v0);
            float ex1 = __expf(v1);
            sum0 += ex0; sum1 += ex1;
            float4 q = *(const float4*)&g_h[(size_t)s * HC + hp * 16 + sub * 4];
            float exs = (sub < 2) ? ex0 : ex1;
            float2 e = make_float2(exs, exs);
            acc0 = ffma2(e, make_float2(q.x, q.y), acc0);
            acc1 = ffma2(e, make_float2(q.z, q.w), acc1);
        }
    }

    acc0 = add2(acc0, shfl_xor_f2(acc0, 4));
    acc0 = add2(acc0, shfl_xor_f2(acc0, 8));
    acc0 = add2(acc0, shfl_xor_f2(acc0, 16));
    acc1 = add2(acc1, shfl_xor_f2(acc1, 4));
    acc1 = add2(acc1, shfl_xor_f2(acc1, 8));
    acc1 = add2(acc1, shfl_xor_f2(acc1, 16));
    sum0 += __shfl_xor_sync(0xffffffffu, sum0, 4);
    sum0 += __shfl_xor_sync(0xffffffffu, sum0, 8);
    sum0 += __shfl_xor_sync(0xffffffffu, sum0, 16);
    sum1 += __shfl_xor_sync(0xffffffffu, sum1, 4);
    sum1 += __shfl_xor_sync(0xffffffffu, sum1, 8);
    sum1 += __shfl_xor_sync(0xffffffffu, sum1, 16);

    float inv = 1.f / ((sub < 2) ? sum0 : sum1);
    int ch = hp * 16 + sub * 4;
    float c0 = acc0.x * inv + b1[ch + 0];
    float c1 = acc0.y * inv + b1[ch + 1];
    float c2 = acc1.x * inv + b1[ch + 2];
    float c3 = acc1.y * inv + b1[ch + 3];
    c0 = (c0 > 0.f) ? c0 : (__expf(c0) - 1.f);
    c1 = (c1 > 0.f) ? c1 : (__expf(c1) - 1.f);
    c2 = (c2 > 0.f) ? c2 : (__expf(c2) - 1.f);
    c3 = (c3 > 0.f) ? c3 : (__expf(c3) - 1.f);
    if (lane < 4)
        *(float4*)&h1s[nl][ch] = make_float4(c0, c1, c2, c3);
    __syncthreads();

    // layer-2 transform: 32 threads (2 nodes x 16 classes); W2 via L1 (no smem preload)
    if (tid < 2 * NC) {
        int tn = tid >> 4;
        int c = tid & 15;
        int gn = blockIdx.x * 2 + tn;
        const float* hp1 = h1s[tn];
        float o = 0.f;
#pragma unroll
        for (int k = 0; k < HC; k++)
            o = fmaf(hp1[k], __ldg(&W2[k * NC + c]), o);
        g_h2[(size_t)gn * NC + c] = o;
        float sv = o * a_src2[c];
        float dv = o * a_dst2[c];
#pragma unroll
        for (int off = 8; off >= 1; off >>= 1) {
            sv += __shfl_xor_sync(0xffffffffu, sv, off);
            dv += __shfl_xor_sync(0xffffffffu, dv, off);
        }
        if (c == 0) {
            g_als2[gn] = sv;
            g_ald2[gn] = dv;
        }
    }
}

// ---------------- layer 2 aggregation + log_softmax (quad-cooperative) ----------------
__global__ void k_agg2(const float* __restrict__ b2, float* __restrict__ outls) {
    int warp = threadIdx.x >> 5;
    int lane = threadIdx.x & 31;
    int n = blockIdx.x * 8 + warp;
    int o0 = n * CAP;
    int deg = min(g_cnt[n], CAP);
    float ald = g_ald2[n];
    int g = lane >> 2;
    int sub = lane & 3;

    float2 acc0 = make_float2(0.f, 0.f), acc1 = make_float2(0.f, 0.f);
    float sumex = 0.f;

    for (int base = 0; base < deg; base += 8) {
        int j = base + g;
        if (j < deg) {
            int s = g_list[o0 + j];
            float v = g_als2[s] + ald;
            v = fmaxf(v, NEG * v);
            float ex = __expf(v);
            sumex += ex;
            float4 q = *(const float4*)&g_h2[(size_t)s * NC + sub * 4];
            float2 e = make_float2(ex, ex);
            acc0 = ffma2(e, make_float2(q.x, q.y), acc0);
            acc1 = ffma2(e, make_float2(q.z, q.w), acc1);
        }
    }

    acc0 = add2(acc0, shfl_xor_f2(acc0, 4));
    acc0 = add2(acc0, shfl_xor_f2(acc0, 8));
    acc0 = add2(acc0, shfl_xor_f2(acc0, 16));
    acc1 = add2(acc1, shfl_xor_f2(acc1, 4));
    acc1 = add2(acc1, shfl_xor_f2(acc1, 8));
    acc1 = add2(acc1, shfl_xor_f2(acc1, 16));
    sumex += __shfl_xor_sync(0xffffffffu, sumex, 4);
    sumex += __shfl_xor_sync(0xffffffffu, sumex, 8);
    sumex += __shfl_xor_sync(0xffffffffu, sumex, 16);

    float inv = 1.f / sumex;
    float z0 = acc0.x * inv + b2[sub * 4 + 0];
    float z1 = acc0.y * inv + b2[sub * 4 + 1];
    float z2 = acc1.x * inv + b2[sub * 4 + 2];
    float z3 = acc1.y * inv + b2[sub * 4 + 3];

    float m = fmaxf(fmaxf(z0, z1), fmaxf(z2, z3));
    m = fmaxf(m, __shfl_xor_sync(0xffffffffu, m, 1));
    m = fmaxf(m, __shfl_xor_sync(0xffffffffu, m, 2));
    float se = __expf(z0 - m) + __expf(z1 - m) + __expf(z2 - m) + __expf(z3 - m);
    se += __shfl_xor_sync(0xffffffffu, se, 1);
    se += __shfl_xor_sync(0xffffffffu, se, 2);
    float lse = m + __logf(se);

    if (lane < 4) {
        *(float4*)&g_z[(size_t)n * NC + sub * 4] = make_float4(z0, z1, z2, z3);
        *(float4*)&outls[(size_t)n * NC + sub * 4] =
            make_float4(z0 - lse, z1 - lse, z2 - lse, z3 - lse);
    }
}

// ---------------- Gram: G = z @ z.T (symmetric — compute upper, store both) ----------------
__global__ void __launch_bounds__(256) k_gram(float* __restrict__ out) {
    int bx = blockIdx.x, by = blockIdx.y;
    if (bx < by) return;   // mirrored by the (by,bx) block's dual store

    __shared__ float zrT[NC][128];
    __shared__ float zcT[NC][128];
    int tid = threadIdx.x;
    int row0 = by * 128;
    int col0 = bx * 128;

    {
        int r = tid >> 1;
        int kg = (tid & 1) * 8;
        float4 v0 = *(const float4*)&g_z[(size_t)(row0 + r) * NC + kg];
        float4 v1 = *(const float4*)&g_z[(size_t)(row0 + r) * NC + kg + 4];
        zrT[kg + 0][r] = v0.x; zrT[kg + 1][r] = v0.y; zrT[kg + 2][r] = v0.z; zrT[kg + 3][r] = v0.w;
        zrT[kg + 4][r] = v1.x; zrT[kg + 5][r] = v1.y; zrT[kg + 6][r] = v1.z; zrT[kg + 7][r] = v1.w;
        float4 u0 = *(const float4*)&g_z[(size_t)(col0 + r) * NC + kg];
        float4 u1 = *(const float4*)&g_z[(size_t)(col0 + r) * NC + kg + 4];
        zcT[kg + 0][r] = u0.x; zcT[kg + 1][r] = u0.y; zcT[kg + 2][r] = u0.z; zcT[kg + 3][r] = u0.w;
        zcT[kg + 4][r] = u1.x; zcT[kg + 5][r] = u1.y; zcT[kg + 6][r] = u1.z; zcT[kg + 7][r] = u1.w;
    }
    __syncthreads();

    int ty = tid >> 4, tx = tid & 15;
    int rr = ty * 8, cc = tx * 8;
    float2 acc[8][4];
#pragma unroll
    for (int i = 0; i < 8; i++)
#pragma unroll
        for (int j = 0; j < 4; j++) acc[i][j] = make_float2(0.f, 0.f);

#pragma unroll
    for (int k = 0; k < NC; k++) {
        float4 a04 = *(const float4*)&zrT[k][rr];
        float4 a48 = *(const float4*)&zrT[k][rr + 4];
        float a[8] = {a04.x, a04.y, a04.z, a04.w, a48.x, a48.y, a48.z, a48.w};
        float4 b04 = *(const float4*)&zcT[k][cc];
        float4 b48 = *(const float4*)&zcT[k][cc + 4];
        float2 b[4] = {make_float2(b04.x, b04.y), make_float2(b04.z, b04.w),
                       make_float2(b48.x, b48.y), make_float2(b48.z, b48.w)};
#pragma unroll
        for (int i = 0; i < 8; i++) {
            float2 adup = make_float2(a[i], a[i]);
#pragma unroll
            for (int j = 0; j < 4; j++)
                acc[i][j] = ffma2(adup, b[j], acc[i][j]);
        }
    }

    // direct tile store
#pragma unroll
    for (int i = 0; i < 8; i++) {
        size_t base = (size_t)(row0 + rr + i) * NN + col0 + cc;
        float4 v0 = make_float4(acc[i][0].x, acc[i][0].y, acc[i][1].x, acc[i][1].y);
        float4 v1 = make_float4(acc[i][2].x, acc[i][2].y, acc[i][3].x, acc[i][3].y);
        __stcs((float4*)&out[base], v0);
        __stcs((float4*)&out[base + 4], v1);
    }

    // mirrored tile store (off-diagonal only): for fixed j, acc[0..7][j] is a
    // contiguous run of mirror-row (col0+cc+j) starting at column row0+rr.
    if (bx > by) {
#pragma unroll
        for (int j = 0; j < 8; j++) {
            int jp = j >> 1;
            bool lo = (j & 1) == 0;
            float v0 = lo ? acc[0][jp].x : acc[0][jp].y;
            float v1 = lo ? acc[1][jp].x : acc[1][jp].y;
            float v2 = lo ? acc[2][jp].x : acc[2][jp].y;
            float v3 = lo ? acc[3][jp].x : acc[3][jp].y;
            float v4 = lo ? acc[4][jp].x : acc[4][jp].y;
            float v5 = lo ? acc[5][jp].x : acc[5][jp].y;
            float v6 = lo ? acc[6][jp].x : acc[6][jp].y;
            float v7 = lo ? acc[7][jp].x : acc[7][jp].y;
            size_t base = (size_t)(col0 + cc + j) * NN + row0 + rr;
            __stcs((float4*)&out[base],     make_float4(v0, v1, v2, v3));
            __stcs((float4*)&out[base + 4], make_float4(v4, v5, v6, v7));
        }
    }
}

// ---------------- launch ----------------
extern "C" void kernel_launch(void* const* d_in, const int* in_sizes, int n_in,
                              void* d_out, int out_size) {
    const float* x      = (const float*)d_in[0];
    const int*   ei     = (const int*)  d_in[1];
    const float* W1     = (const float*)d_in[2];
    const float* a_src1 = (const float*)d_in[3];
    const float* a_dst1 = (const float*)d_in[4];
    const float* b1     = (const float*)d_in[5];
    const float* W2     = (const float*)d_in[6];
    const float* a_src2 = (const float*)d_in[7];
    const float* a_dst2 = (const float*)d_in[8];
    const float* b2     = (const float*)d_in[9];
    float* out = (float*)d_out;

    static cudaStream_t sA = nullptr;
    static cudaEvent_t evFork = nullptr, evA = nullptr;
    if (sA == nullptr) {
        cudaStreamCreateWithFlags(&sA, cudaStreamNonBlocking);
        cudaEventCreateWithFlags(&evFork, cudaEventDisableTiming);
        cudaEventCreateWithFlags(&evA, cudaEventDisableTiming);
    }

    cudaEventRecord(evFork, 0);
    cudaStreamWaitEvent(sA, evFork, 0);

    k_init<<<NN / 256, 256, 0, sA>>>();                 // launch 1
    k_gemm1<<<NN / 64, 256>>>(x, W1, a_src1, a_dst1);   // launch 2 (main)
    k_scatter<<<EE / 4 / 256, 256, 0, sA>>>(ei);        // launch 3
    cudaEventRecord(evA, sA);
    cudaStreamWaitEvent(0, evA, 0);

    k_agg1<<<NN / 2, 256>>>(b1, W2, a_src2, a_dst2);    // launch 4  <- profiled slot
    k_agg2<<<NN / 8, 256>>>(b2, out);                   // launch 5
    k_gram<<<dim3(NN / 128, NN / 128), 256>>>(out + (size_t)NN * NC);  // launch 6
}

// round 13
// speedup vs baseline: 1.1424x; 1.0029x over previous
#include <cuda_runtime.h>
#include <math.h>

#define NN      8192
#define FIN     512
#define HH      8
#define C1      8
#define HC      64      // H*C1
#define NC      16
#define EE      262144
#define CAP     128     // padded adjacency capacity, 512B-aligned rows
#define NEG     0.2f

// ---------------- packed f32x2 helpers ----------------
__device__ __forceinline__ float2 ffma2(float2 a, float2 b, float2 c) {
    unsigned long long ra = *reinterpret_cast<unsigned long long*>(&a);
    unsigned long long rb = *reinterpret_cast<unsigned long long*>(&b);
    unsigned long long rc = *reinterpret_cast<unsigned long long*>(&c);
    unsigned long long rd;
    asm("fma.rn.f32x2 %0, %1, %2, %3;" : "=l"(rd) : "l"(ra), "l"(rb), "l"(rc));
    return *reinterpret_cast<float2*>(&rd);
}
__device__ __forceinline__ float2 add2(float2 a, float2 b) {
    unsigned long long ra = *reinterpret_cast<unsigned long long*>(&a);
    unsigned long long rb = *reinterpret_cast<unsigned long long*>(&b);
    unsigned long long rd;
    asm("add.rn.f32x2 %0, %1, %2;" : "=l"(rd) : "l"(ra), "l"(rb));
    return *reinterpret_cast<float2*>(&rd);
}
__device__ __forceinline__ float2 shfl_xor_f2(float2 v, int m) {
    float2 r;
    r.x = __shfl_xor_sync(0xffffffffu, v.x, m);
    r.y = __shfl_xor_sync(0xffffffffu, v.y, m);
    return r;
}

// ---------------- device scratch ----------------
__device__ int   g_cnt [NN];
__device__ int   g_list[NN * CAP];

__device__ float g_h   [NN * HC];
__device__ float g_als1[NN * HH];
__device__ float g_ald1[NN * HH];
__device__ float g_h2  [NN * NC];
__device__ float g_als2[NN];
__device__ float g_ald2[NN];
__device__ float g_z   [NN * NC];

// ---------------- adjacency build ----------------
__global__ void k_init() {
    int i = blockIdx.x * blockDim.x + threadIdx.x;
    if (i < NN) {
        g_cnt[i] = 1;            // self-loop pre-appended
        g_list[i * CAP] = i;
    }
}

__global__ void k_scatter(const int* __restrict__ ei) {
    int t = blockIdx.x * blockDim.x + threadIdx.x;
    if (t >= EE / 4) return;
    int e = t * 4;
    int4 s = __ldcs((const int4*)&ei[e]);
    int4 d = __ldcs((const int4*)&ei[EE + e]);
    int p0 = min(atomicAdd(&g_cnt[d.x], 1), CAP - 1);
    g_list[d.x * CAP + p0] = s.x;
    int p1 = min(atomicAdd(&g_cnt[d.y], 1), CAP - 1);
    g_list[d.y * CAP + p1] = s.y;
    int p2 = min(atomicAdd(&g_cnt[d.z], 1), CAP - 1);
    g_list[d.z * CAP + p2] = s.z;
    int p3 = min(atomicAdd(&g_cnt[d.w], 1), CAP - 1);
    g_list[d.w * CAP + p3] = s.w;
}

// ---------------- GEMM1 + fused logits (double-buffered smem, 1 sync/chunk) ----------------
__global__ void __launch_bounds__(256) k_gemm1(const float* __restrict__ x,
                                               const float* __restrict__ W1,
                                               const float* __restrict__ a_src,
                                               const float* __restrict__ a_dst) {
    __shared__ float xsT[2][16][68];
    __shared__ float ws[2][16][64];
    __shared__ float hs[64][68];
    __shared__ float sa[2 * HC];
    int tid = threadIdx.x;
    int row0 = blockIdx.x * 64;
    int tr = tid >> 4;
    int tc = tid & 15;

    if (tid < 2 * HC) sa[tid] = (tid < HC) ? a_src[tid] : a_dst[tid - HC];

    float2 acc[4][2];
#pragma unroll
    for (int i = 0; i < 4; i++)
#pragma unroll
        for (int j = 0; j < 2; j++) acc[i][j] = make_float2(0.f, 0.f);

    int lr = tid >> 2, lc = (tid & 3) * 4;
    int wr = tid >> 4, wc = (tid & 15) * 4;

    // fill stage 0
    {
        float4 xv = *(const float4*)&x[(size_t)(row0 + lr) * FIN + lc];
        float4 wv = *(const float4*)&W1[(size_t)wr * HC + wc];
        xsT[0][lc + 0][lr] = xv.x; xsT[0][lc + 1][lr] = xv.y;
        xsT[0][lc + 2][lr] = xv.z; xsT[0][lc + 3][lr] = xv.w;
        *(float4*)&ws[0][wr][wc] = wv;
    }
    __syncthreads();

    for (int c = 0; c < FIN / 16; c++) {
        int cur = c & 1;
        float4 xv, wv;
        bool more = (c + 1 < FIN / 16);
        if (more) {
            int k0 = (c + 1) * 16;
            xv = *(const float4*)&x[(size_t)(row0 + lr) * FIN + k0 + lc];
            wv = *(const float4*)&W1[(size_t)(k0 + wr) * HC + wc];
        }
#pragma unroll
        for (int kk = 0; kk < 16; kk++) {
            float4 av = *(const float4*)&xsT[cur][kk][tr * 4];
            float4 bv = *(const float4*)&ws[cur][kk][tc * 4];
            float2 b0 = make_float2(bv.x, bv.y);
            float2 b1 = make_float2(bv.z, bv.w);
            float a[4] = {av.x, av.y, av.z, av.w};
#pragma unroll
            for (int i = 0; i < 4; i++) {
                float2 ad = make_float2(a[i], a[i]);
                acc[i][0] = ffma2(ad, b0, acc[i][0]);
                acc[i][1] = ffma2(ad, b1, acc[i][1]);
            }
        }
        if (more) {
            int nxt = cur ^ 1;
            xsT[nxt][lc + 0][lr] = xv.x; xsT[nxt][lc + 1][lr] = xv.y;
            xsT[nxt][lc + 2][lr] = xv.z; xsT[nxt][lc + 3][lr] = xv.w;
            *(float4*)&ws[nxt][wr][wc] = wv;
        }
        __syncthreads();
    }
#pragma unroll
    for (int i = 0; i < 4; i++) {
        int r = tr * 4 + i;
        float4 v = make_float4(acc[i][0].x, acc[i][0].y, acc[i][1].x, acc[i][1].y);
        *(float4*)&g_h[(size_t)(row0 + r) * HC + tc * 4] = v;
        *(float4*)&hs[r][tc * 4] = v;
    }
    __syncthreads();

    if (tid < 64) {
        const float* hp = hs[tid];
        float als[HH], ald[HH];
#pragma unroll
        for (int h = 0; h < HH; h++) {
            float s = 0.f, d = 0.f;
#pragma unroll
            for (int c2 = 0; c2 < C1; c2++) {
                float hv = hp[h * C1 + c2];
                s = fmaf(hv, sa[h * C1 + c2], s);
                d = fmaf(hv, sa[HC + h * C1 + c2], d);
            }
            als[h] = s; ald[h] = d;
        }
        size_t b = (size_t)(row0 + tid) * HH;
        *(float4*)&g_als1[b]     = make_float4(als[0], als[1], als[2], als[3]);
        *(float4*)&g_als1[b + 4] = make_float4(als[4], als[5], als[6], als[7]);
        *(float4*)&g_ald1[b]     = make_float4(ald[0], ald[1], ald[2], ald[3]);
        *(float4*)&g_ald1[b + 4] = make_float4(ald[4], ald[5], ald[6], ald[7]);
    }
}

// ---------------- fused agg1 + layer2 transform (pipelined quad-gather) ----------------
// Block = 512 threads = 4 nodes x 4 warps; warp handles 2 heads (16 channels).
__global__ void __launch_bounds__(512) k_agg1(const float* __restrict__ b1,
                                              const float* __restrict__ W2,
                                              const float* __restrict__ a_src2,
                                              const float* __restrict__ a_dst2) {
    __shared__ float h1s[4][HC];
    int tid = threadIdx.x;
    int warp = tid >> 5;
    int lane = tid & 31;
    int nl = warp >> 2;                  // local node 0..3
    int hp = warp & 3;
    int n = blockIdx.x * 4 + nl;
    int o0 = n * CAP;
    int deg = min(g_cnt[n], CAP);
    int g = lane >> 2;
    int sub = lane & 3;

    float2 aldv = *(const float2*)&g_ald1[n * HH + 2 * hp];

    float2 acc0 = make_float2(0.f, 0.f), acc1 = make_float2(0.f, 0.f);
    float sum0 = 0.f, sum1 = 0.f;

    // pipeline stage 0
    bool valid = g < deg;
    int s = valid ? g_list[o0 + g] : 0;
    float2 alsv = *(const float2*)&g_als1[s * HH + 2 * hp];
    float4 q = *(const float4*)&g_h[(size_t)s * HC + hp * 16 + sub * 4];

    for (int base = 0; base < deg; base += 8) {
        // prefetch next batch while computing current
        int jn = base + 8 + g;
        bool vn = jn < deg;
        int sn = vn ? g_list[o0 + jn] : 0;
        float2 alsn = *(const float2*)&g_als1[sn * HH + 2 * hp];
        float4 qn = *(const float4*)&g_h[(size_t)sn * HC + hp * 16 + sub * 4];

        float v0 = alsv.x + aldv.x;
        float v1 = alsv.y + aldv.y;
        v0 = fmaxf(v0, NEG * v0);
        v1 = fmaxf(v1, NEG * v1);
        float ex0 = valid ? __expf(v0) : 0.f;
        float ex1 = valid ? __expf(v1) : 0.f;
        sum0 += ex0; sum1 += ex1;
        float exs = (sub < 2) ? ex0 : ex1;
        float2 e = make_float2(exs, exs);
        acc0 = ffma2(e, make_float2(q.x, q.y), acc0);
        acc1 = ffma2(e, make_float2(q.z, q.w), acc1);

        valid = vn; s = sn; alsv = alsn; q = qn;
    }

    acc0 = add2(acc0, shfl_xor_f2(acc0, 4));
    acc0 = add2(acc0, shfl_xor_f2(acc0, 8));
    acc0 = add2(acc0, shfl_xor_f2(acc0, 16));
    acc1 = add2(acc1, shfl_xor_f2(acc1, 4));
    acc1 = add2(acc1, shfl_xor_f2(acc1, 8));
    acc1 = add2(acc1, shfl_xor_f2(acc1, 16));
    sum0 += __shfl_xor_sync(0xffffffffu, sum0, 4);
    sum0 += __shfl_xor_sync(0xffffffffu, sum0, 8);
    sum0 += __shfl_xor_sync(0xffffffffu, sum0, 16);
    sum1 += __shfl_xor_sync(0xffffffffu, sum1, 4);
    sum1 += __shfl_xor_sync(0xffffffffu, sum1, 8);
    sum1 += __shfl_xor_sync(0xffffffffu, sum1, 16);

    float inv = 1.f / ((sub < 2) ? sum0 : sum1);
    int ch = hp * 16 + sub * 4;
    float c0 = acc0.x * inv + b1[ch + 0];
    float c1 = acc0.y * inv + b1[ch + 1];
    float c2 = acc1.x * inv + b1[ch + 2];
    float c3 = acc1.y * inv + b1[ch + 3];
    c0 = (c0 > 0.f) ? c0 : (__expf(c0) - 1.f);
    c1 = (c1 > 0.f) ? c1 : (__expf(c1) - 1.f);
    c2 = (c2 > 0.f) ? c2 : (__expf(c2) - 1.f);
    c3 = (c3 > 0.f) ? c3 : (__expf(c3) - 1.f);
    if (lane < 4)
        *(float4*)&h1s[nl][ch] = make_float4(c0, c1, c2, c3);
    __syncthreads();

    // layer-2 transform: 64 threads (4 nodes x 16 classes); W2 via L1
    if (tid < 4 * NC) {
        int tn = tid >> 4;
        int c = tid & 15;
        int gn = blockIdx.x * 4 + tn;
        const float* hp1 = h1s[tn];
        float o = 0.f;
#pragma unroll
        for (int k = 0; k < HC; k++)
            o = fmaf(hp1[k], __ldg(&W2[k * NC + c]), o);
        g_h2[(size_t)gn * NC + c] = o;
        float sv = o * a_src2[c];
        float dv = o * a_dst2[c];
#pragma unroll
        for (int off = 8; off >= 1; off >>= 1) {
            sv += __shfl_xor_sync(0xffffffffu, sv, off);
            dv += __shfl_xor_sync(0xffffffffu, dv, off);
        }
        if (c == 0) {
            g_als2[gn] = sv;
            g_ald2[gn] = dv;
        }
    }
}

// ---------------- layer 2 aggregation + log_softmax (pipelined quad-gather) ----------------
__global__ void k_agg2(const float* __restrict__ b2, float* __restrict__ outls) {
    int warp = threadIdx.x >> 5;
    int lane = threadIdx.x & 31;
    int n = blockIdx.x * 8 + warp;
    int o0 = n * CAP;
    int deg = min(g_cnt[n], CAP);
    float ald = g_ald2[n];
    int g = lane >> 2;
    int sub = lane & 3;

    float2 acc0 = make_float2(0.f, 0.f), acc1 = make_float2(0.f, 0.f);
    float sumex = 0.f;

    bool valid = g < deg;
    int s = valid ? g_list[o0 + g] : 0;
    float alss = g_als2[s];
    float4 q = *(const float4*)&g_h2[(size_t)s * NC + sub * 4];

    for (int base = 0; base < deg; base += 8) {
        int jn = base + 8 + g;
        bool vn = jn < deg;
        int sn = vn ? g_list[o0 + jn] : 0;
        float alsn = g_als2[sn];
        float4 qn = *(const float4*)&g_h2[(size_t)sn * NC + sub * 4];

        float v = alss + ald;
        v = fmaxf(v, NEG * v);
        float ex = valid ? __expf(v) : 0.f;
        sumex += ex;
        float2 e = make_float2(ex, ex);
        acc0 = ffma2(e, make_float2(q.x, q.y), acc0);
        acc1 = ffma2(e, make_float2(q.z, q.w), acc1);

        valid = vn; s = sn; alss = alsn; q = qn;
    }

    acc0 = add2(acc0, shfl_xor_f2(acc0, 4));
    acc0 = add2(acc0, shfl_xor_f2(acc0, 8));
    acc0 = add2(acc0, shfl_xor_f2(acc0, 16));
    acc1 = add2(acc1, shfl_xor_f2(acc1, 4));
    acc1 = add2(acc1, shfl_xor_f2(acc1, 8));
    acc1 = add2(acc1, shfl_xor_f2(acc1, 16));
    sumex += __shfl_xor_sync(0xffffffffu, sumex, 4);
    sumex += __shfl_xor_sync(0xffffffffu, sumex, 8);
    sumex += __shfl_xor_sync(0xffffffffu, sumex, 16);

    float inv = 1.f / sumex;
    float z0 = acc0.x * inv + b2[sub * 4 + 0];
    float z1 = acc0.y * inv + b2[sub * 4 + 1];
    float z2 = acc1.x * inv + b2[sub * 4 + 2];
    float z3 = acc1.y * inv + b2[sub * 4 + 3];

    float m = fmaxf(fmaxf(z0, z1), fmaxf(z2, z3));
    m = fmaxf(m, __shfl_xor_sync(0xffffffffu, m, 1));
    m = fmaxf(m, __shfl_xor_sync(0xffffffffu, m, 2));
    float se = __expf(z0 - m) + __expf(z1 - m) + __expf(z2 - m) + __expf(z3 - m);
    se += __shfl_xor_sync(0xffffffffu, se, 1);
    se += __shfl_xor_sync(0xffffffffu, se, 2);
    float lse = m + __logf(se);

    if (lane < 4) {
        *(float4*)&g_z[(size_t)n * NC + sub * 4] = make_float4(z0, z1, z2, z3);
        *(float4*)&outls[(size_t)n * NC + sub * 4] =
            make_float4(z0 - lse, z1 - lse, z2 - lse, z3 - lse);
    }
}

// ---------------- Gram: G = z @ z.T (symmetric — compute upper, store both) ----------------
__global__ void __launch_bounds__(256) k_gram(float* __restrict__ out) {
    int bx = blockIdx.x, by = blockIdx.y;
    if (bx < by) return;

    __shared__ float zrT[NC][128];
    __shared__ float zcT[NC][128];
    int tid = threadIdx.x;
    int row0 = by * 128;
    int col0 = bx * 128;

    {
        int r = tid >> 1;
        int kg = (tid & 1) * 8;
        float4 v0 = *(const float4*)&g_z[(size_t)(row0 + r) * NC + kg];
        float4 v1 = *(const float4*)&g_z[(size_t)(row0 + r) * NC + kg + 4];
        zrT[kg + 0][r] = v0.x; zrT[kg + 1][r] = v0.y; zrT[kg + 2][r] = v0.z; zrT[kg + 3][r] = v0.w;
        zrT[kg + 4][r] = v1.x; zrT[kg + 5][r] = v1.y; zrT[kg + 6][r] = v1.z; zrT[kg + 7][r] = v1.w;
        float4 u0 = *(const float4*)&g_z[(size_t)(col0 + r) * NC + kg];
        float4 u1 = *(const float4*)&g_z[(size_t)(col0 + r) * NC + kg + 4];
        zcT[kg + 0][r] = u0.x; zcT[kg + 1][r] = u0.y; zcT[kg + 2][r] = u0.z; zcT[kg + 3][r] = u0.w;
        zcT[kg + 4][r] = u1.x; zcT[kg + 5][r] = u1.y; zcT[kg + 6][r] = u1.z; zcT[kg + 7][r] = u1.w;
    }
    __syncthreads();

    int ty = tid >> 4, tx = tid & 15;
    int rr = ty * 8, cc = tx * 8;
    float2 acc[8][4];
#pragma unroll
    for (int i = 0; i < 8; i++)
#pragma unroll
        for (int j = 0; j < 4; j++) acc[i][j] = make_float2(0.f, 0.f);

#pragma unroll
    for (int k = 0; k < NC; k++) {
        float4 a04 = *(const float4*)&zrT[k][rr];
        float4 a48 = *(const float4*)&zrT[k][rr + 4];
        float a[8] = {a04.x, a04.y, a04.z, a04.w, a48.x, a48.y, a48.z, a48.w};
        float4 b04 = *(const float4*)&zcT[k][cc];
        float4 b48 = *(const float4*)&zcT[k][cc + 4];
        float2 b[4] = {make_float2(b04.x, b04.y), make_float2(b04.z, b04.w),
                       make_float2(b48.x, b48.y), make_float2(b48.z, b48.w)};
#pragma unroll
        for (int i = 0; i < 8; i++) {
            float2 adup = make_float2(a[i], a[i]);
#pragma unroll
            for (int j = 0; j < 4; j++)
                acc[i][j] = ffma2(adup, b[j], acc[i][j]);
        }
    }

#pragma unroll
    for (int i = 0; i < 8; i++) {
        size_t base = (size_t)(row0 + rr + i) * NN + col0 + cc;
        float4 v0 = make_float4(acc[i][0].x, acc[i][0].y, acc[i][1].x, acc[i][1].y);
        float4 v1 = make_float4(acc[i][2].x, acc[i][2].y, acc[i][3].x, acc[i][3].y);
        __stcs((float4*)&out[base], v0);
        __stcs((float4*)&out[base + 4], v1);
    }

    if (bx > by) {
#pragma unroll
        for (int j = 0; j < 8; j++) {
            int jp = j >> 1;
            bool lo = (j & 1) == 0;
            float v0 = lo ? acc[0][jp].x : acc[0][jp].y;
            float v1 = lo ? acc[1][jp].x : acc[1][jp].y;
            float v2 = lo ? acc[2][jp].x : acc[2][jp].y;
            float v3 = lo ? acc[3][jp].x : acc[3][jp].y;
            float v4 = lo ? acc[4][jp].x : acc[4][jp].y;
            float v5 = lo ? acc[5][jp].x : acc[5][jp].y;
            float v6 = lo ? acc[6][jp].x : acc[6][jp].y;
            float v7 = lo ? acc[7][jp].x : acc[7][jp].y;
            size_t base = (size_t)(col0 + cc + j) * NN + row0 + rr;
            __stcs((float4*)&out[base],     make_float4(v0, v1, v2, v3));
            __stcs((float4*)&out[base + 4], make_float4(v4, v5, v6, v7));
        }
    }
}

// ---------------- launch ----------------
extern "C" void kernel_launch(void* const* d_in, const int* in_sizes, int n_in,
                              void* d_out, int out_size) {
    const float* x      = (const float*)d_in[0];
    const int*   ei     = (const int*)  d_in[1];
    const float* W1     = (const float*)d_in[2];
    const float* a_src1 = (const float*)d_in[3];
    const float* a_dst1 = (const float*)d_in[4];
    const float* b1     = (const float*)d_in[5];
    const float* W2     = (const float*)d_in[6];
    const float* a_src2 = (const float*)d_in[7];
    const float* a_dst2 = (const float*)d_in[8];
    const float* b2     = (const float*)d_in[9];
    float* out = (float*)d_out;

    static cudaStream_t sA = nullptr;
    static cudaEvent_t evFork = nullptr, evA = nullptr;
    if (sA == nullptr) {
        cudaStreamCreateWithFlags(&sA, cudaStreamNonBlocking);
        cudaEventCreateWithFlags(&evFork, cudaEventDisableTiming);
        cudaEventCreateWithFlags(&evA, cudaEventDisableTiming);
    }

    cudaEventRecord(evFork, 0);
    cudaStreamWaitEvent(sA, evFork, 0);

    k_init<<<NN / 256, 256, 0, sA>>>();                 // launch 1
    k_gemm1<<<NN / 64, 256>>>(x, W1, a_src1, a_dst1);   // launch 2 (main)
    k_scatter<<<EE / 4 / 256, 256, 0, sA>>>(ei);        // launch 3
    cudaEventRecord(evA, sA);
    cudaStreamWaitEvent(0, evA, 0);

    k_agg1<<<NN / 4, 512>>>(b1, W2, a_src2, a_dst2);    // launch 4  <- profiled slot
    k_agg2<<<NN / 8, 256>>>(b2, out);                   // launch 5
    k_gram<<<dim3(NN / 128, NN / 128), 256>>>(out + (size_t)NN * NC);  // launch 6
}

// round 17
// speedup vs baseline: 1.1787x; 1.0318x over previous
#include <cuda_runtime.h>
#include <math.h>

#define NN      8192
#define FIN     512
#define HH      8
#define C1      8
#define HC      64      // H*C1
#define NC      16
#define EE      262144
#define CAP     128     // padded adjacency capacity, 512B-aligned rows
#define NEG     0.2f

// ---------------- packed f32x2 helpers ----------------
__device__ __forceinline__ float2 ffma2(float2 a, float2 b, float2 c) {
    unsigned long long ra = *reinterpret_cast<unsigned long long*>(&a);
    unsigned long long rb = *reinterpret_cast<unsigned long long*>(&b);
    unsigned long long rc = *reinterpret_cast<unsigned long long*>(&c);
    unsigned long long rd;
    asm("fma.rn.f32x2 %0, %1, %2, %3;" : "=l"(rd) : "l"(ra), "l"(rb), "l"(rc));
    return *reinterpret_cast<float2*>(&rd);
}
__device__ __forceinline__ float2 add2(float2 a, float2 b) {
    unsigned long long ra = *reinterpret_cast<unsigned long long*>(&a);
    unsigned long long rb = *reinterpret_cast<unsigned long long*>(&b);
    unsigned long long rd;
    asm("add.rn.f32x2 %0, %1, %2;" : "=l"(rd) : "l"(ra), "l"(rb));
    return *reinterpret_cast<float2*>(&rd);
}
__device__ __forceinline__ float2 shfl_xor_f2(float2 v, int m) {
    float2 r;
    r.x = __shfl_xor_sync(0xffffffffu, v.x, m);
    r.y = __shfl_xor_sync(0xffffffffu, v.y, m);
    return r;
}

// ---------------- device scratch ----------------
__device__ int   g_cnt [NN];
__device__ int   g_list[NN * CAP];

__device__ float g_h   [NN * HC];
__device__ float g_ald1[NN * HH];
__device__ float g_h2  [NN * NC];
__device__ float g_ald2[NN];
__device__ float g_z   [NN * NC];

// ---------------- adjacency build ----------------
__global__ void k_init() {
    int i = blockIdx.x * blockDim.x + threadIdx.x;
    if (i < NN) {
        g_cnt[i] = 1;            // self-loop pre-appended
        g_list[i * CAP] = i;
    }
}

__global__ void k_scatter(const int* __restrict__ ei) {
    int t = blockIdx.x * blockDim.x + threadIdx.x;
    if (t >= EE / 4) return;
    int e = t * 4;
    int4 s = __ldcs((const int4*)&ei[e]);
    int4 d = __ldcs((const int4*)&ei[EE + e]);
    int p0 = min(atomicAdd(&g_cnt[d.x], 1), CAP - 1);
    g_list[d.x * CAP + p0] = s.x;
    int p1 = min(atomicAdd(&g_cnt[d.y], 1), CAP - 1);
    g_list[d.y * CAP + p1] = s.y;
    int p2 = min(atomicAdd(&g_cnt[d.z], 1), CAP - 1);
    g_list[d.z * CAP + p2] = s.z;
    int p3 = min(atomicAdd(&g_cnt[d.w], 1), CAP - 1);
    g_list[d.w * CAP + p3] = s.w;
}

// ---------------- GEMM1 + fused dst-logits (double-buffered smem) ----------------
__global__ void __launch_bounds__(256) k_gemm1(const float* __restrict__ x,
                                               const float* __restrict__ W1,
                                               const float* __restrict__ a_dst) {
    __shared__ float xsT[2][16][68];
    __shared__ float ws[2][16][64];
    __shared__ float hs[64][68];
    __shared__ float sa[HC];
    int tid = threadIdx.x;
    int row0 = blockIdx.x * 64;
    int tr = tid >> 4;
    int tc = tid & 15;

    if (tid < HC) sa[tid] = a_dst[tid];

    float2 acc[4][2];
#pragma unroll
    for (int i = 0; i < 4; i++)
#pragma unroll
        for (int j = 0; j < 2; j++) acc[i][j] = make_float2(0.f, 0.f);

    int lr = tid >> 2, lc = (tid & 3) * 4;
    int wr = tid >> 4, wc = (tid & 15) * 4;

    {
        float4 xv = *(const float4*)&x[(size_t)(row0 + lr) * FIN + lc];
        float4 wv = *(const float4*)&W1[(size_t)wr * HC + wc];
        xsT[0][lc + 0][lr] = xv.x; xsT[0][lc + 1][lr] = xv.y;
        xsT[0][lc + 2][lr] = xv.z; xsT[0][lc + 3][lr] = xv.w;
        *(float4*)&ws[0][wr][wc] = wv;
    }
    __syncthreads();

    for (int c = 0; c < FIN / 16; c++) {
        int cur = c & 1;
        float4 xv, wv;
        bool more = (c + 1 < FIN / 16);
        if (more) {
            int k0 = (c + 1) * 16;
            xv = *(const float4*)&x[(size_t)(row0 + lr) * FIN + k0 + lc];
            wv = *(const float4*)&W1[(size_t)(k0 + wr) * HC + wc];
        }
#pragma unroll
        for (int kk = 0; kk < 16; kk++) {
            float4 av = *(const float4*)&xsT[cur][kk][tr * 4];
            float4 bv = *(const float4*)&ws[cur][kk][tc * 4];
            float2 b0 = make_float2(bv.x, bv.y);
            float2 b1 = make_float2(bv.z, bv.w);
            float a[4] = {av.x, av.y, av.z, av.w};
#pragma unroll
            for (int i = 0; i < 4; i++) {
                float2 ad = make_float2(a[i], a[i]);
                acc[i][0] = ffma2(ad, b0, acc[i][0]);
                acc[i][1] = ffma2(ad, b1, acc[i][1]);
            }
        }
        if (more) {
            int nxt = cur ^ 1;
            xsT[nxt][lc + 0][lr] = xv.x; xsT[nxt][lc + 1][lr] = xv.y;
            xsT[nxt][lc + 2][lr] = xv.z; xsT[nxt][lc + 3][lr] = xv.w;
            *(float4*)&ws[nxt][wr][wc] = wv;
        }
        __syncthreads();
    }
#pragma unroll
    for (int i = 0; i < 4; i++) {
        int r = tr * 4 + i;
        float4 v = make_float4(acc[i][0].x, acc[i][0].y, acc[i][1].x, acc[i][1].y);
        *(float4*)&g_h[(size_t)(row0 + r) * HC + tc * 4] = v;
        *(float4*)&hs[r][tc * 4] = v;
    }
    __syncthreads();

    // epilogue: dst-logits only (src logits computed on-the-fly in agg1)
    if (tid < 64) {
        const float* hp = hs[tid];
        float ald[HH];
#pragma unroll
        for (int h = 0; h < HH; h++) {
            float d = 0.f;
#pragma unroll
            for (int c2 = 0; c2 < C1; c2++)
                d = fmaf(hp[h * C1 + c2], sa[h * C1 + c2], d);
            ald[h] = d;
        }
        size_t b = (size_t)(row0 + tid) * HH;
        *(float4*)&g_ald1[b]     = make_float4(ald[0], ald[1], ald[2], ald[3]);
        *(float4*)&g_ald1[b + 4] = make_float4(ald[4], ald[5], ald[6], ald[7]);
    }
}

// ---------------- fused agg1 + layer2 transform (quad-gather, on-the-fly src logits) ----------------
// Block = 256 threads = 2 nodes x 4 warps; warp handles 2 heads (16 channels).
// WARP-UNIFORM loop: every lane executes every batch (index clamped, invalid
// contribution zeroed) so the in-loop shuffles are always full-warp.
__global__ void __launch_bounds__(256) k_agg1(const float* __restrict__ a_src1,
                                              const float* __restrict__ b1,
                                              const float* __restrict__ W2,
                                              const float* __restrict__ a_src2,
                                              const float* __restrict__ a_dst2) {
    __shared__ float h1s[2][HC];
    int tid = threadIdx.x;
    int warp = tid >> 5;
    int lane = tid & 31;
    int nl = warp >> 2;
    int hp = warp & 3;
    int n = blockIdx.x * 2 + nl;
    int o0 = n * CAP;
    int deg = min(g_cnt[n], CAP);   // >= 1 (self-loop)
    int g = lane >> 2;          // neighbor group 0..7
    int sub = lane & 3;         // float4 slice within 64B chunk

    float2 aldv = *(const float2*)&g_ald1[n * HH + 2 * hp];
    float aldh = (sub < 2) ? aldv.x : aldv.y;                 // this lane's head dst-logit
    float4 as4 = *(const float4*)&a_src1[hp * 16 + sub * 4];  // a_src slice for this lane

    float2 acc0 = make_float2(0.f, 0.f), acc1 = make_float2(0.f, 0.f);
    float sumex = 0.f;

    for (int base = 0; base < deg; base += 8) {
        int j = base + g;
        bool valid = j < deg;
        int jc = valid ? j : (deg - 1);              // clamped, always in-bounds
        int s = g_list[o0 + jc];
        float4 q = *(const float4*)&g_h[(size_t)s * HC + hp * 16 + sub * 4];
        // on-the-fly src logit for this lane's head: pair-sum of 4-elem dots
        float part = q.x * as4.x + q.y * as4.y + q.z * as4.z + q.w * as4.w;
        float als = part + __shfl_xor_sync(0xffffffffu, part, 1);   // uniform: all lanes
        float v = als + aldh;
        v = fmaxf(v, NEG * v);
        float ex = valid ? __expf(v) : 0.f;
        sumex += ex;
        float2 e = make_float2(ex, ex);
        acc0 = ffma2(e, make_float2(q.x, q.y), acc0);
        acc1 = ffma2(e, make_float2(q.z, q.w), acc1);
    }

    // reduce across the 8 neighbor groups (lane bits 2,3,4)
    acc0 = add2(acc0, shfl_xor_f2(acc0, 4));
    acc0 = add2(acc0, shfl_xor_f2(acc0, 8));
    acc0 = add2(acc0, shfl_xor_f2(acc0, 16));
    acc1 = add2(acc1, shfl_xor_f2(acc1, 4));
    acc1 = add2(acc1, shfl_xor_f2(acc1, 8));
    acc1 = add2(acc1, shfl_xor_f2(acc1, 16));
    sumex += __shfl_xor_sync(0xffffffffu, sumex, 4);
    sumex += __shfl_xor_sync(0xffffffffu, sumex, 8);
    sumex += __shfl_xor_sync(0xffffffffu, sumex, 16);
    // lane's sumex is its own head's total

    float inv = 1.f / sumex;
    int ch = hp * 16 + sub * 4;
    float c0 = acc0.x * inv + b1[ch + 0];
    float c1 = acc0.y * inv + b1[ch + 1];
    float c2 = acc1.x * inv + b1[ch + 2];
    float c3 = acc1.y * inv + b1[ch + 3];
    c0 = (c0 > 0.f) ? c0 : (__expf(c0) - 1.f);
    c1 = (c1 > 0.f) ? c1 : (__expf(c1) - 1.f);
    c2 = (c2 > 0.f) ? c2 : (__expf(c2) - 1.f);
    c3 = (c3 > 0.f) ? c3 : (__expf(c3) - 1.f);
    if (lane < 4)
        *(float4*)&h1s[nl][ch] = make_float4(c0, c1, c2, c3);
    __syncthreads();

    // layer-2 transform: 32 threads (2 nodes x 16 classes); W2 via L1
    if (tid < 2 * NC) {
        int tn = tid >> 4;
        int c = tid & 15;
        int gn = blockIdx.x * 2 + tn;
        const float* hp1 = h1s[tn];
        float o = 0.f;
#pragma unroll
        for (int k = 0; k < HC; k++)
            o = fmaf(hp1[k], __ldg(&W2[k * NC + c]), o);
        g_h2[(size_t)gn * NC + c] = o;
        float dv = o * a_dst2[c];
#pragma unroll
        for (int off = 8; off >= 1; off >>= 1)
            dv += __shfl_xor_sync(0xffffffffu, dv, off);
        if (c == 0) g_ald2[gn] = dv;
    }
}

// ---------------- layer 2 aggregation + log_softmax (uniform quad-gather) ----------------
__global__ void k_agg2(const float* __restrict__ a_src2,
                       const float* __restrict__ b2, float* __restrict__ outls) {
    int warp = threadIdx.x >> 5;
    int lane = threadIdx.x & 31;
    int n = blockIdx.x * 8 + warp;
    int o0 = n * CAP;
    int deg = min(g_cnt[n], CAP);
    float ald = g_ald2[n];
    int g = lane >> 2;
    int sub = lane & 3;

    float4 as4 = *(const float4*)&a_src2[sub * 4];

    float2 acc0 = make_float2(0.f, 0.f), acc1 = make_float2(0.f, 0.f);
    float sumex = 0.f;

    for (int base = 0; base < deg; base += 8) {
        int j = base + g;
        bool valid = j < deg;
        int jc = valid ? j : (deg - 1);
        int s = g_list[o0 + jc];
        float4 q = *(const float4*)&g_h2[(size_t)s * NC + sub * 4];
        float part = q.x * as4.x + q.y * as4.y + q.z * as4.z + q.w * as4.w;
        part += __shfl_xor_sync(0xffffffffu, part, 1);
        part += __shfl_xor_sync(0xffffffffu, part, 2);   // full 16-dot across quad
        float v = part + ald;
        v = fmaxf(v, NEG * v);
        float ex = valid ? __expf(v) : 0.f;
        sumex += ex;
        float2 e = make_float2(ex, ex);
        acc0 = ffma2(e, make_float2(q.x, q.y), acc0);
        acc1 = ffma2(e, make_float2(q.z, q.w), acc1);
    }

    acc0 = add2(acc0, shfl_xor_f2(acc0, 4));
    acc0 = add2(acc0, shfl_xor_f2(acc0, 8));
    acc0 = add2(acc0, shfl_xor_f2(acc0, 16));
    acc1 = add2(acc1, shfl_xor_f2(acc1, 4));
    acc1 = add2(acc1, shfl_xor_f2(acc1, 8));
    acc1 = add2(acc1, shfl_xor_f2(acc1, 16));
    sumex += __shfl_xor_sync(0xffffffffu, sumex, 4);
    sumex += __shfl_xor_sync(0xffffffffu, sumex, 8);
    sumex += __shfl_xor_sync(0xffffffffu, sumex, 16);

    float inv = 1.f / sumex;
    float z0 = acc0.x * inv + b2[sub * 4 + 0];
    float z1 = acc0.y * inv + b2[sub * 4 + 1];
    float z2 = acc1.x * inv + b2[sub * 4 + 2];
    float z3 = acc1.y * inv + b2[sub * 4 + 3];

    float m = fmaxf(fmaxf(z0, z1), fmaxf(z2, z3));
    m = fmaxf(m, __shfl_xor_sync(0xffffffffu, m, 1));
    m = fmaxf(m, __shfl_xor_sync(0xffffffffu, m, 2));
    float se = __expf(z0 - m) + __expf(z1 - m) + __expf(z2 - m) + __expf(z3 - m);
    se += __shfl_xor_sync(0xffffffffu, se, 1);
    se += __shfl_xor_sync(0xffffffffu, se, 2);
    float lse = m + __logf(se);

    if (lane < 4) {
        *(float4*)&g_z[(size_t)n * NC + sub * 4] = make_float4(z0, z1, z2, z3);
        *(float4*)&outls[(size_t)n * NC + sub * 4] =
            make_float4(z0 - lse, z1 - lse, z2 - lse, z3 - lse);
    }
}

// ---------------- Gram: G = z @ z.T, full compute, coalesced streaming stores ----------------
__global__ void __launch_bounds__(256) k_gram(float* __restrict__ out) {
    __shared__ float zrT[NC][128];
    __shared__ float zcT[NC][128];
    int tid = threadIdx.x;
    int row0 = blockIdx.y * 128;
    int col0 = blockIdx.x * 128;

    {
        int r = tid >> 1;
        int kg = (tid & 1) * 8;
        float4 v0 = *(const float4*)&g_z[(size_t)(row0 + r) * NC + kg];
        float4 v1 = *(const float4*)&g_z[(size_t)(row0 + r) * NC + kg + 4];
        zrT[kg + 0][r] = v0.x; zrT[kg + 1][r] = v0.y; zrT[kg + 2][r] = v0.z; zrT[kg + 3][r] = v0.w;
        zrT[kg + 4][r] = v1.x; zrT[kg + 5][r] = v1.y; zrT[kg + 6][r] = v1.z; zrT[kg + 7][r] = v1.w;
        float4 u0 = *(const float4*)&g_z[(size_t)(col0 + r) * NC + kg];
        float4 u1 = *(const float4*)&g_z[(size_t)(col0 + r) * NC + kg + 4];
        zcT[kg + 0][r] = u0.x; zcT[kg + 1][r] = u0.y; zcT[kg + 2][r] = u0.z; zcT[kg + 3][r] = u0.w;
        zcT[kg + 4][r] = u1.x; zcT[kg + 5][r] = u1.y; zcT[kg + 6][r] = u1.z; zcT[kg + 7][r] = u1.w;
    }
    __syncthreads();

    int ty = tid >> 4, tx = tid & 15;
    int rr = ty * 8, cc = tx * 8;
    float2 acc[8][4];
#pragma unroll
    for (int i = 0; i < 8; i++)
#pragma unroll
        for (int j = 0; j < 4; j++) acc[i][j] = make_float2(0.f, 0.f);

#pragma unroll
    for (int k = 0; k < NC; k++) {
        float4 a04 = *(const float4*)&zrT[k][rr];
        float4 a48 = *(const float4*)&zrT[k][rr + 4];
        float a[8] = {a04.x, a04.y, a04.z, a04.w, a48.x, a48.y, a48.z, a48.w};
        float4 b04 = *(const float4*)&zcT[k][cc];
        float4 b48 = *(const float4*)&zcT[k][cc + 4];
        float2 b[4] = {make_float2(b04.x, b04.y), make_float2(b04.z, b04.w),
                       make_float2(b48.x, b48.y), make_float2(b48.z, b48.w)};
#pragma unroll
        for (int i = 0; i < 8; i++) {
            float2 adup = make_float2(a[i], a[i]);
#pragma unroll
            for (int j = 0; j < 4; j++)
                acc[i][j] = ffma2(adup, b[j], acc[i][j]);
        }
    }

#pragma unroll
    for (int i = 0; i < 8; i++) {
        size_t base = (size_t)(row0 + rr + i) * NN + col0 + cc;
        float4 v0 = make_float4(acc[i][0].x, acc[i][0].y, acc[i][1].x, acc[i][1].y);
        float4 v1 = make_float4(acc[i][2].x, acc[i][2].y, acc[i][3].x, acc[i][3].y);
        __stcs((float4*)&out[base], v0);
        __stcs((float4*)&out[base + 4], v1);
    }
}

// ---------------- launch ----------------
extern "C" void kernel_launch(void* const* d_in, const int* in_sizes, int n_in,
                              void* d_out, int out_size) {
    const float* x      = (const float*)d_in[0];
    const int*   ei     = (const int*)  d_in[1];
    const float* W1     = (const float*)d_in[2];
    const float* a_src1 = (const float*)d_in[3];
    const float* a_dst1 = (const float*)d_in[4];
    const float* b1     = (const float*)d_in[5];
    const float* W2     = (const float*)d_in[6];
    const float* a_src2 = (const float*)d_in[7];
    const float* a_dst2 = (const float*)d_in[8];
    const float* b2     = (const float*)d_in[9];
    float* out = (float*)d_out;

    static cudaStream_t sA = nullptr;
    static cudaEvent_t evFork = nullptr, evA = nullptr;
    if (sA == nullptr) {
        cudaStreamCreateWithFlags(&sA, cudaStreamNonBlocking);
        cudaEventCreateWithFlags(&evFork, cudaEventDisableTiming);
        cudaEventCreateWithFlags(&evA, cudaEventDisableTiming);
    }

    cudaEventRecord(evFork, 0);
    cudaStreamWaitEvent(sA, evFork, 0);

    k_init<<<NN / 256, 256, 0, sA>>>();                 // launch 1
    k_gemm1<<<NN / 64, 256>>>(x, W1, a_dst1);           // launch 2 (main)
    k_scatter<<<EE / 4 / 256, 256, 0, sA>>>(ei);        // launch 3
    cudaEventRecord(evA, sA);
    cudaStreamWaitEvent(0, evA, 0);

    k_agg1<<<NN / 2, 256>>>(a_src1, b1, W2, a_src2, a_dst2);  // launch 4 <- profiled
    k_agg2<<<NN / 8, 256>>>(a_src2, b2, out);           // launch 5
    k_gram<<<dim3(NN / 128, NN / 128), 256>>>(out + (size_t)NN * NC);  // launch 6
}